// round 9
// baseline (speedup 1.0000x reference)
#include <cuda_runtime.h>
#include <cuda_bf16.h>
#include <cstdint>
#include <cstddef>

#define LL   4096
#define CC   32
#define NCH  128
#define BHT  16
#define SDK  132
#define OUT_ELEMS  ((size_t)BHT * LL * 128)
#define S_ELEMS    ((size_t)BHT * 128 * 128)

typedef unsigned long long ull;

__device__ float g_wqT[(size_t)BHT * NCH * 128 * 64];
__device__ float g_kR [(size_t)BHT * NCH * 32 * 128];
__device__ float g_at2[(size_t)BHT * NCH * 32 * 32];
__device__ float g_u2 [(size_t)BHT * 8 * NCH * 32 * 16];
__device__ unsigned int g_flag[BHT * NCH];

__device__ __forceinline__ float dot4(float4 a, float4 b) {
    return a.x * b.x + a.y * b.y + a.z * b.z + a.w * b.w;
}
__device__ __forceinline__ ull pk1(float x) {
    ull r; asm("mov.b64 %0,{%1,%1};" : "=l"(r) : "f"(x)); return r;
}
__device__ __forceinline__ void fm2(ull& a, ull b, ull c) {
    asm("fma.rn.f32x2 %0,%1,%2,%3;" : "=l"(a) : "l"(b), "l"(c), "l"(a));
}
__device__ __forceinline__ ull ad2r(ull a, ull b) {
    ull r; asm("add.rn.f32x2 %0,%1,%2;" : "=l"(r) : "l"(a), "l"(b)); return r;
}
__device__ __forceinline__ float2 upk(ull a) {
    float2 f; asm("mov.b64 {%0,%1},%2;" : "=f"(f.x), "=f"(f.y) : "l"(a)); return f;
}
__device__ __forceinline__ uint32_t s2u(const void* p) {
    return (uint32_t)__cvta_generic_to_shared(p);
}
__device__ __forceinline__ void mbar_init(uint32_t m, uint32_t c) {
    asm volatile("mbarrier.init.shared.b64 [%0], %1;" :: "r"(m), "r"(c) : "memory");
}
__device__ __forceinline__ void mbar_expect(uint32_t m, uint32_t b) {
    asm volatile("mbarrier.arrive.expect_tx.shared.b64 _, [%0], %1;" :: "r"(m), "r"(b) : "memory");
}
__device__ __forceinline__ void mbar_wait(uint32_t m, uint32_t p) {
    asm volatile(
        "{\n\t.reg .pred P;\n\tW%=:\n\t"
        "mbarrier.try_wait.parity.acquire.cta.shared::cta.b64 P, [%0], %1, 0x989680;\n\t"
        "@P bra D%=;\n\tbra W%=;\n\tD%=:\n\t}" :: "r"(m), "r"(p) : "memory");
}
__device__ __forceinline__ void bulkcp(uint32_t d, const void* s, uint32_t b, uint32_t m) {
    asm volatile("cp.async.bulk.shared::cta.global.mbarrier::complete_tx::bytes [%0], [%1], %2, [%3];"
        :: "r"(d), "l"(s), "r"(b), "r"(m) : "memory");
}
__device__ __forceinline__ void setflag(unsigned int* p) {
    asm volatile("st.release.gpu.u32 [%0], %1;" :: "l"(p), "r"(1u) : "memory");
}
__device__ __forceinline__ void waitflag(const unsigned int* p) {
    unsigned int v;
    do { asm volatile("ld.acquire.gpu.u32 %0, [%1];" : "=r"(v) : "l"(p)); } while (!v);
    asm volatile("fence.proxy.async;" ::: "memory");
}

__global__ void reset_kernel() { g_flag[blockIdx.x * 256 + threadIdx.x] = 0u; }

// smem (floats): mbars 8 | sS 2048 | po 512 | kR 4096 | 2 x (wq 8192 + at 1024 + u 512)
#define BUF_F  9728
#define OFF_AT 8192
#define OFF_U  9216
#define TXM    38912u
#define SMEMF  (8 + 2048 + 512 + 4096 + 2 * BUF_F)
#define SMEMB  (SMEMF * 4)

__global__ __launch_bounds__(256, 2) void fused_kernel(
    const float* __restrict__ gq, const float* __restrict__ gk,
    const float* __restrict__ gv, const float* __restrict__ gbeta,
    float* __restrict__ out, float* __restrict__ Sout)
{
    extern __shared__ float sm[];
    const int t = threadIdx.x;

    if (blockIdx.x >= 128) {
        // ================= phase1 producer (persistent) =================
        float* sq = sm; float* sk = sm + 4224; float* sv = sm + 8448;
        float* sA = sm + 12672; float* sbeta = sm + 13728;
        float* sqs = sm + 13760; float* sks = sm + 13792;
        float* sAt = sm + 13824; float* stg = sm + 14848;

        for (int lc = (int)blockIdx.x - 128; lc < NCH * BHT; lc += 148) {
            const int ch = lc >> 4, bh = lc & 15;
            __syncthreads();
            const size_t gbase = ((size_t)bh * LL + (size_t)ch * CC) * 128;
            {
                const float4* q4 = (const float4*)(gq + gbase);
                const float4* k4 = (const float4*)(gk + gbase);
                const float4* v4 = (const float4*)(gv + gbase);
                for (int idx = t; idx < 1024; idx += 256) {
                    int r = idx >> 5, c4 = idx & 31;
                    ((float4*)(sq + r * SDK))[c4] = q4[idx];
                    ((float4*)(sk + r * SDK))[c4] = k4[idx];
                    ((float4*)(sv + r * SDK))[c4] = v4[idx];
                }
            }
            if (t < CC) sbeta[t] = gbeta[(size_t)bh * LL + (size_t)ch * CC + t];
            __syncthreads();
            {
                int row = t >> 3, seg = t & 7;
                const float4* qr = (const float4*)(sq + row * SDK) + seg * 4;
                const float4* kr = (const float4*)(sk + row * SDK) + seg * 4;
                float s2q = 0.f, s2k = 0.f;
                #pragma unroll
                for (int i2 = 0; i2 < 4; i2++) {
                    float4 a = qr[i2]; s2q += dot4(a, a);
                    float4 b = kr[i2]; s2k += dot4(b, b);
                }
                #pragma unroll
                for (int off = 4; off; off >>= 1) {
                    s2q += __shfl_down_sync(0xffffffffu, s2q, off, 8);
                    s2k += __shfl_down_sync(0xffffffffu, s2k, off, 8);
                }
                if (seg == 0) { sqs[row] = rsqrtf(s2q + 1e-6f); sks[row] = rsqrtf(s2k + 1e-6f); }
            }
            __syncthreads();
            {
                int row = t >> 3, seg = t & 7;
                float a = sqs[row], b = sks[row];
                float4* qr = (float4*)(sq + row * SDK) + seg * 4;
                float4* kr = (float4*)(sk + row * SDK) + seg * 4;
                #pragma unroll
                for (int i2 = 0; i2 < 4; i2++) {
                    float4 x = qr[i2]; x.x *= a; x.y *= a; x.z *= a; x.w *= a; qr[i2] = x;
                    float4 y = kr[i2]; y.x *= b; y.y *= b; y.z *= b; y.w *= b; kr[i2] = y;
                }
            }
            __syncthreads();

            const size_t krb = ((size_t)(bh * NCH + ch)) * 4096;
            for (int idx = t; idx < 1024; idx += 256) {
                int r = idx >> 5, c4 = idx & 31;
                *(float4*)(g_kR + krb + (size_t)r * 128 + (c4 << 2)) =
                    *(const float4*)(sk + r * SDK + (c4 << 2));
            }
            {   // q-hat -> stg cols 32..63 (k-major)
                int d = t >> 1, half = t & 1, i0q = half * 16;
                #pragma unroll
                for (int ii = 0; ii < 16; ii += 4) {
                    float4 a = make_float4(sq[(i0q + ii) * SDK + d], sq[(i0q + ii + 1) * SDK + d],
                                           sq[(i0q + ii + 2) * SDK + d], sq[(i0q + ii + 3) * SDK + d]);
                    *(float4*)(stg + d * 64 + 32 + i0q + ii) = a;
                }
            }
            {   // dots -> sA (strict lower), attn -> sAt (swizzled)
                int ti = t >> 4, tj = t & 15;
                int i0 = 2 * ti, j0 = 2 * tj;
                ull pkk00 = 0, pkk01 = 0, pkk10 = 0, pkk11 = 0;
                ull pqk00 = 0, pqk01 = 0, pqk10 = 0, pqk11 = 0;
                const ulonglong2* ki0 = (const ulonglong2*)(sk + i0 * SDK);
                const ulonglong2* ki1 = (const ulonglong2*)(sk + (i0 + 1) * SDK);
                const ulonglong2* kj0 = (const ulonglong2*)(sk + j0 * SDK);
                const ulonglong2* kj1 = (const ulonglong2*)(sk + (j0 + 1) * SDK);
                const ulonglong2* qi0 = (const ulonglong2*)(sq + i0 * SDK);
                const ulonglong2* qi1 = (const ulonglong2*)(sq + (i0 + 1) * SDK);
                #pragma unroll 8
                for (int d4 = 0; d4 < 32; d4++) {
                    ulonglong2 A0 = ki0[d4], A1 = ki1[d4];
                    ulonglong2 B0 = kj0[d4], B1 = kj1[d4];
                    ulonglong2 C0 = qi0[d4], C1 = qi1[d4];
                    fm2(pkk00, A0.x, B0.x); fm2(pkk00, A0.y, B0.y);
                    fm2(pkk01, A0.x, B1.x); fm2(pkk01, A0.y, B1.y);
                    fm2(pkk10, A1.x, B0.x); fm2(pkk10, A1.y, B0.y);
                    fm2(pkk11, A1.x, B1.x); fm2(pkk11, A1.y, B1.y);
                    fm2(pqk00, C0.x, B0.x); fm2(pqk00, C0.y, B0.y);
                    fm2(pqk01, C0.x, B1.x); fm2(pqk01, C0.y, B1.y);
                    fm2(pqk10, C1.x, B0.x); fm2(pqk10, C1.y, B0.y);
                    fm2(pqk11, C1.x, B1.x); fm2(pqk11, C1.y, B1.y);
                }
                float2 e;
                e = upk(pkk00); float dkk00 = e.x + e.y;
                e = upk(pkk01); float dkk01 = e.x + e.y;
                e = upk(pkk10); float dkk10 = e.x + e.y;
                e = upk(pkk11); float dkk11 = e.x + e.y;
                e = upk(pqk00); float dqk00 = e.x + e.y;
                e = upk(pqk01); float dqk01 = e.x + e.y;
                e = upk(pqk10); float dqk10 = e.x + e.y;
                e = upk(pqk11); float dqk11 = e.x + e.y;
                float bi0 = sbeta[i0], bi1 = sbeta[i0 + 1];
                sA[i0 * 33 + j0]           = (i0 > j0)         ? -bi0 * dkk00 : 0.f;
                sA[i0 * 33 + j0 + 1]       = (i0 > j0 + 1)     ? -bi0 * dkk01 : 0.f;
                sA[(i0 + 1) * 33 + j0]     = (i0 + 1 > j0)     ? -bi1 * dkk10 : 0.f;
                sA[(i0 + 1) * 33 + j0 + 1] = (i0 + 1 > j0 + 1) ? -bi1 * dkk11 : 0.f;
                #define ATW(ii, jj, val) sAt[(ii) * 32 + (((((jj) >> 2) ^ ((ii) & 7)) << 2) + ((jj) & 3))] = (val)
                ATW(i0,     j0,     (i0 >= j0)         ? dqk00 : 0.f);
                ATW(i0,     j0 + 1, (i0 >= j0 + 1)     ? dqk01 : 0.f);
                ATW(i0 + 1, j0,     (i0 + 1 >= j0)     ? dqk10 : 0.f);
                ATW(i0 + 1, j0 + 1, (i0 + 1 >= j0 + 1) ? dqk11 : 0.f);
                #undef ATW
            }
            __syncthreads();

            if (t < 32) {   // forward substitution (reference order)
                const int lane = t;
                for (int i = 1; i < CC; i++) {
                    float a = sA[i * 33 + lane];
                    float f = a;
                    for (int k = 1; k < i; k++) {
                        float bk = __shfl_sync(0xffffffffu, a, k);
                        f += bk * sA[k * 33 + lane];
                    }
                    __syncwarp();
                    if (lane < i) sA[i * 33 + lane] = f;
                    __syncwarp();
                }
                sA[lane * 33 + lane] = 1.0f;
            }
            __syncthreads();
            for (int idx = t; idx < 1024; idx += 256) {
                int i = idx >> 5, j = idx & 31;
                sA[i * 33 + j] *= sbeta[j];
            }
            __syncthreads();

            {   // u -> g_u2 direct; w -> stg cols 0..31
                int p = t >> 4, dseg = t & 15;
                int i0 = 2 * p, d0 = 8 * dseg;
                ulonglong2 u0a = {0,0}, u0b = {0,0}, u1a = {0,0}, u1b = {0,0};
                ulonglong2 w0a = {0,0}, w0b = {0,0}, w1a = {0,0}, w1b = {0,0};
                #pragma unroll 4
                for (int j = 0; j < CC; j++) {
                    ull A0 = pk1(sA[i0 * 33 + j]);
                    ull A1 = pk1(sA[(i0 + 1) * 33 + j]);
                    ulonglong2 va = *(const ulonglong2*)(sv + j * SDK + d0);
                    ulonglong2 vb = *(const ulonglong2*)(sv + j * SDK + d0 + 4);
                    ulonglong2 ka = *(const ulonglong2*)(sk + j * SDK + d0);
                    ulonglong2 kb = *(const ulonglong2*)(sk + j * SDK + d0 + 4);
                    fm2(u0a.x, A0, va.x); fm2(u0a.y, A0, va.y);
                    fm2(u0b.x, A0, vb.x); fm2(u0b.y, A0, vb.y);
                    fm2(u1a.x, A1, va.x); fm2(u1a.y, A1, va.y);
                    fm2(u1b.x, A1, vb.x); fm2(u1b.y, A1, vb.y);
                    fm2(w0a.x, A0, ka.x); fm2(w0a.y, A0, ka.y);
                    fm2(w0b.x, A0, kb.x); fm2(w0b.y, A0, kb.y);
                    fm2(w1a.x, A1, ka.x); fm2(w1a.y, A1, ka.y);
                    fm2(w1b.x, A1, kb.x); fm2(w1b.y, A1, kb.y);
                }
                int sl = d0 >> 4, off = d0 & 15;
                size_t ub2 = (((size_t)(bh * 8 + sl)) * NCH + ch) * 512;
                *(ulonglong2*)(g_u2 + ub2 + (size_t)i0 * 16 + off)           = u0a;
                *(ulonglong2*)(g_u2 + ub2 + (size_t)i0 * 16 + off + 4)       = u0b;
                *(ulonglong2*)(g_u2 + ub2 + (size_t)(i0 + 1) * 16 + off)     = u1a;
                *(ulonglong2*)(g_u2 + ub2 + (size_t)(i0 + 1) * 16 + off + 4) = u1b;
                float w0arr[8], w1arr[8];
                float2 e;
                e = upk(w0a.x); w0arr[0] = e.x; w0arr[1] = e.y;
                e = upk(w0a.y); w0arr[2] = e.x; w0arr[3] = e.y;
                e = upk(w0b.x); w0arr[4] = e.x; w0arr[5] = e.y;
                e = upk(w0b.y); w0arr[6] = e.x; w0arr[7] = e.y;
                e = upk(w1a.x); w1arr[0] = e.x; w1arr[1] = e.y;
                e = upk(w1a.y); w1arr[2] = e.x; w1arr[3] = e.y;
                e = upk(w1b.x); w1arr[4] = e.x; w1arr[5] = e.y;
                e = upk(w1b.y); w1arr[6] = e.x; w1arr[7] = e.y;
                #pragma unroll
                for (int dd = 0; dd < 8; dd++)
                    *(float2*)(stg + (d0 + dd) * 64 + i0) = make_float2(w0arr[dd], w1arr[dd]);
            }
            __syncthreads();

            // coalesced copies
            const size_t wqb = ((size_t)(bh * NCH + ch)) * 8192;
            for (int f4 = t; f4 < 2048; f4 += 256)
                *(float4*)(g_wqT + wqb + ((size_t)f4 << 2)) = *(const float4*)(stg + (f4 << 2));
            {
                size_t ab = ((size_t)(bh * NCH + ch)) * 1024;
                *(float4*)(g_at2 + ab + ((size_t)t << 2)) = *(const float4*)(sAt + (t << 2));
            }
            __threadfence();
            __syncthreads();
            if (t == 0) setflag(&g_flag[bh * NCH + ch]);
        }
        return;
    }

    // ================= phase2 consumer =================
    float* sS   = sm + 8;
    float* po   = sm + 2056;
    float* kRb  = sm + 2568;
    float* bufs = sm + 6664;

    const int slice = blockIdx.x & 7;
    const int bh    = blockIdx.x >> 3;
    const int c0    = slice * 16;

    const int lane = t & 31, warp = t >> 5;
    const int tl = lane & 7, kg = lane >> 3;
    const int tile = warp * 8 + tl;
    const int tr = tile & 15, tc = tile >> 4;
    const int i0 = tr << 2;
    const int cb4 = tc << 2;

    const uint32_t mb0 = s2u(sm), mb1 = mb0 + 8, kmb = mb0 + 16;

    for (int idx = t; idx < 2048; idx += 256) sS[idx] = 0.f;
    if (t == 0) { mbar_init(mb0, 1); mbar_init(mb1, 1); mbar_init(kmb, 1); }
    __syncthreads();

    const size_t cb0 = (size_t)bh * NCH;
    const size_t ublk = ((size_t)(bh * 8 + slice)) * NCH;
    if (t == 0) {
        waitflag(&g_flag[bh * NCH]);
        mbar_expect(mb0, TXM);
        bulkcp(s2u(bufs),          g_wqT + cb0 * 8192, 32768, mb0);
        bulkcp(s2u(bufs + OFF_AT), g_at2 + cb0 * 1024, 4096, mb0);
        bulkcp(s2u(bufs + OFF_U),  g_u2  + ublk * 512, 2048, mb0);
        mbar_expect(kmb, 16384);
        bulkcp(s2u(kRb), g_kR + cb0 * 4096, 16384, kmb);
    }

    for (int ch = 0; ch < NCH; ch++) {
        const int b = ch & 1;
        float* B  = bufs + b * BUF_F;
        float* bu = B + OFF_U;

        __syncthreads();
        if (t == 0) {
            if (ch > 0) {
                mbar_expect(kmb, 16384);
                bulkcp(s2u(kRb), g_kR + (cb0 + ch) * 4096, 16384, kmb);
            }
            if (ch + 1 < NCH) {
                uint32_t mb = b ? mb0 : mb1;
                float* B2 = bufs + (b ^ 1) * BUF_F;
                const size_t cb = cb0 + ch + 1;
                waitflag(&g_flag[bh * NCH + ch + 1]);
                mbar_expect(mb, TXM);
                bulkcp(s2u(B2),          g_wqT + cb * 8192, 32768, mb);
                bulkcp(s2u(B2 + OFF_AT), g_at2 + cb * 1024, 4096, mb);
                bulkcp(s2u(B2 + OFF_U),  g_u2  + (ublk + ch + 1) * 512, 2048, mb);
            }
        }
        mbar_wait(b ? mb1 : mb0, (ch >> 1) & 1);

        // P = [w;q]@S : 4x4 tile, k-split-4
        ull a00 = 0, a01 = 0, a10 = 0, a11 = 0, a20 = 0, a21 = 0, a30 = 0, a31 = 0;
        {
            const float* wp = B + (kg << 5) * 64 + i0;
            const float* sbase = sS + (kg << 5) * 16;
            #pragma unroll
            for (int k = 0; k < 32; k++) {
                float4 w4 = *(const float4*)(wp + k * 64);
                const int phys = ((tc ^ ((k >> 2) & 3) ^ kg) << 2);
                ulonglong2 s2 = *(const ulonglong2*)(sbase + k * 16 + phys);
                fm2(a00, pk1(w4.x), s2.x); fm2(a01, pk1(w4.x), s2.y);
                fm2(a10, pk1(w4.y), s2.x); fm2(a11, pk1(w4.y), s2.y);
                fm2(a20, pk1(w4.z), s2.x); fm2(a21, pk1(w4.z), s2.y);
                fm2(a30, pk1(w4.w), s2.x); fm2(a31, pk1(w4.w), s2.y);
            }
        }
        #pragma unroll
        for (int m = 8; m <= 16; m <<= 1) {
            a00 = ad2r(a00, __shfl_xor_sync(0xffffffffu, a00, m));
            a01 = ad2r(a01, __shfl_xor_sync(0xffffffffu, a01, m));
            a10 = ad2r(a10, __shfl_xor_sync(0xffffffffu, a10, m));
            a11 = ad2r(a11, __shfl_xor_sync(0xffffffffu, a11, m));
            a20 = ad2r(a20, __shfl_xor_sync(0xffffffffu, a20, m));
            a21 = ad2r(a21, __shfl_xor_sync(0xffffffffu, a21, m));
            a30 = ad2r(a30, __shfl_xor_sync(0xffffffffu, a30, m));
            a31 = ad2r(a31, __shfl_xor_sync(0xffffffffu, a31, m));
        }
        if (kg == 0) {
            float2 l0 = upk(a00), h0 = upk(a01);
            float2 l1 = upk(a10), h1 = upk(a11);
            float2 l2 = upk(a20), h2 = upk(a21);
            float2 l3 = upk(a30), h3 = upk(a31);
            if (tr < 8) {
                float* up = bu + i0 * 16 + cb4;
                float4 u0 = *(const float4*)(up);
                float4 u1 = *(const float4*)(up + 16);
                float4 u2 = *(const float4*)(up + 32);
                float4 u3 = *(const float4*)(up + 48);
                u0.x -= l0.x; u0.y -= l0.y; u0.z -= h0.x; u0.w -= h0.y;
                u1.x -= l1.x; u1.y -= l1.y; u1.z -= h1.x; u1.w -= h1.y;
                u2.x -= l2.x; u2.y -= l2.y; u2.z -= h2.x; u2.w -= h2.y;
                u3.x -= l3.x; u3.y -= l3.y; u3.z -= h3.x; u3.w -= h3.y;
                *(float4*)(up)      = u0;
                *(float4*)(up + 16) = u1;
                *(float4*)(up + 32) = u2;
                *(float4*)(up + 48) = u3;
            } else {
                float* pp = po + (i0 - 32) * 16 + cb4;
                *(float4*)(pp)      = make_float4(l0.x, l0.y, h0.x, h0.y);
                *(float4*)(pp + 16) = make_float4(l1.x, l1.y, h1.x, h1.y);
                *(float4*)(pp + 32) = make_float4(l2.x, l2.y, h2.x, h2.y);
                *(float4*)(pp + 48) = make_float4(l3.x, l3.y, h3.x, h3.y);
            }
        }
        __syncthreads();

        if (t < 128) {
            mbar_wait(kmb, ch & 1);
            const int rt = t >> 2, ct = t & 3;
            const int rb = rt << 2;
            const int physc = ((ct ^ ((rt ^ (rt >> 3)) & 3)) << 2);
            float* sp0 = sS + rb * 16 + physc;
            ulonglong2 s0 = *(const ulonglong2*)(sp0);
            ulonglong2 s1 = *(const ulonglong2*)(sp0 + 16);
            ulonglong2 s2v = *(const ulonglong2*)(sp0 + 32);
            ulonglong2 s3 = *(const ulonglong2*)(sp0 + 48);
            const float* kp = kRb + rb;
            const float* up2 = bu + (ct << 2);
            #pragma unroll 8
            for (int j = 0; j < 32; j++) {
                float4 k4 = *(const float4*)kp;
                ulonglong2 u2 = *(const ulonglong2*)up2;
                fm2(s0.x,  pk1(k4.x), u2.x); fm2(s0.y,  pk1(k4.x), u2.y);
                fm2(s1.x,  pk1(k4.y), u2.x); fm2(s1.y,  pk1(k4.y), u2.y);
                fm2(s2v.x, pk1(k4.z), u2.x); fm2(s2v.y, pk1(k4.z), u2.y);
                fm2(s3.x,  pk1(k4.w), u2.x); fm2(s3.y,  pk1(k4.w), u2.y);
                kp += 128; up2 += 16;
            }
            *(ulonglong2*)(sp0)      = s0;
            *(ulonglong2*)(sp0 + 16) = s1;
            *(ulonglong2*)(sp0 + 32) = s2v;
            *(ulonglong2*)(sp0 + 48) = s3;
        } else {
            const int ii2 = (t - 128) >> 2, cq = t & 3;
            const int asw = ii2 & 7;
            ulonglong2 acc = *(const ulonglong2*)(po + ii2 * 16 + (cq << 2));
            const float* atr = B + OFF_AT + ii2 * 32;
            const float* Up = bu + (cq << 2);
            #pragma unroll
            for (int j4 = 0; j4 < 8; j4++) {
                float4 a4 = *(const float4*)(atr + ((j4 ^ asw) << 2));
                const float* u0p = Up + (j4 << 6);
                ulonglong2 U0 = *(const ulonglong2*)(u0p);
                ulonglong2 U1 = *(const ulonglong2*)(u0p + 16);
                ulonglong2 U2 = *(const ulonglong2*)(u0p + 32);
                ulonglong2 U3 = *(const ulonglong2*)(u0p + 48);
                fm2(acc.x, pk1(a4.x), U0.x); fm2(acc.y, pk1(a4.x), U0.y);
                fm2(acc.x, pk1(a4.y), U1.x); fm2(acc.y, pk1(a4.y), U1.y);
                fm2(acc.x, pk1(a4.z), U2.x); fm2(acc.y, pk1(a4.z), U2.y);
                fm2(acc.x, pk1(a4.w), U3.x); fm2(acc.y, pk1(a4.w), U3.y);
            }
            float2 f0 = upk(acc.x), f1 = upk(acc.y);
            size_t off = ((size_t)bh * LL + (size_t)ch * CC + ii2) * 128 + c0 + (cq << 2);
            *(float4*)(out + off) = make_float4(f0.x, f0.y, f1.x, f1.y);
        }
    }

    if (Sout != nullptr) {
        __syncthreads();
        size_t sb = (size_t)bh * 128 * 128;
        for (int idx = t; idx < 2048; idx += 256) {
            int r = idx >> 4, c = idx & 15;
            int phys = ((((c >> 2) ^ ((r >> 2) & 3) ^ ((r >> 5) & 3)) & 3) << 2) + (c & 3);
            Sout[sb + (size_t)r * 128 + c0 + c] = sS[r * 16 + phys];
        }
    }
}

extern "C" void kernel_launch(void* const* d_in, const int* in_sizes, int n_in,
                              void* d_out, int out_size)
{
    const float* q    = (const float*)d_in[0];
    const float* k    = (const float*)d_in[1];
    const float* v    = (const float*)d_in[2];
    const float* beta = (const float*)d_in[3];
    float* out = (float*)d_out;
    float* Sout = ((size_t)out_size >= OUT_ELEMS + S_ELEMS) ? (out + OUT_ELEMS) : nullptr;

    cudaFuncSetAttribute(fused_kernel, cudaFuncAttributeMaxDynamicSharedMemorySize, SMEMB);
    reset_kernel<<<8, 256>>>();
    fused_kernel<<<276, 256, SMEMB>>>(q, k, v, beta, out, Sout);
}

// round 11
// speedup vs baseline: 1.0283x; 1.0283x over previous
#include <cuda_runtime.h>
#include <cuda_bf16.h>
#include <cstdint>
#include <cstddef>

#define LL   4096
#define CC   32
#define NCH  128
#define BHT  16
#define SDK  132
#define OUT_ELEMS  ((size_t)BHT * LL * 128)
#define S_ELEMS    ((size_t)BHT * 128 * 128)

typedef unsigned long long ull;

__device__ float g_wqT[(size_t)BHT * NCH * 128 * 64];
__device__ float g_kR [(size_t)BHT * NCH * 32 * 128];
__device__ float g_at2[(size_t)BHT * NCH * 32 * 32];
__device__ float g_u2 [(size_t)BHT * 8 * NCH * 32 * 16];

__device__ __forceinline__ float dot4(float4 a, float4 b) {
    return a.x * b.x + a.y * b.y + a.z * b.z + a.w * b.w;
}
__device__ __forceinline__ ull pk1(float x) {
    ull r; asm("mov.b64 %0,{%1,%1};" : "=l"(r) : "f"(x)); return r;
}
__device__ __forceinline__ void fm2(ull& a, ull b, ull c) {
    asm("fma.rn.f32x2 %0,%1,%2,%3;" : "=l"(a) : "l"(b), "l"(c), "l"(a));
}
__device__ __forceinline__ ull ad2r(ull a, ull b) {
    ull r; asm("add.rn.f32x2 %0,%1,%2;" : "=l"(r) : "l"(a), "l"(b)); return r;
}
__device__ __forceinline__ float2 upk(ull a) {
    float2 f; asm("mov.b64 {%0,%1},%2;" : "=f"(f.x), "=f"(f.y) : "l"(a)); return f;
}
__device__ __forceinline__ uint32_t s2u(const void* p) {
    return (uint32_t)__cvta_generic_to_shared(p);
}
__device__ __forceinline__ void mbar_init(uint32_t m, uint32_t c) {
    asm volatile("mbarrier.init.shared.b64 [%0], %1;" :: "r"(m), "r"(c) : "memory");
}
__device__ __forceinline__ void mbar_expect(uint32_t m, uint32_t b) {
    asm volatile("mbarrier.arrive.expect_tx.shared.b64 _, [%0], %1;" :: "r"(m), "r"(b) : "memory");
}
__device__ __forceinline__ void mbar_wait(uint32_t m, uint32_t p) {
    asm volatile(
        "{\n\t.reg .pred P;\n\tW%=:\n\t"
        "mbarrier.try_wait.parity.acquire.cta.shared::cta.b64 P, [%0], %1, 0x989680;\n\t"
        "@P bra D%=;\n\tbra W%=;\n\tD%=:\n\t}" :: "r"(m), "r"(p) : "memory");
}
__device__ __forceinline__ void bulkcp(uint32_t d, const void* s, uint32_t b, uint32_t m) {
    asm volatile("cp.async.bulk.shared::cta.global.mbarrier::complete_tx::bytes [%0], [%1], %2, [%3];"
        :: "r"(d), "l"(s), "r"(b), "r"(m) : "memory");
}

// =====================================================================
// Phase 1: grid (NCH, BHT), 256 threads. All scattered outputs staged
// in smem; globals written with coalesced linear copies.
// smem floats: sq 4224 | sk 4224 | sv 4224 | sA 1056 | beta/qs/ks 96 |
//              sAt 1024 | stg 8192   = 23040 floats (92160 B)
// =====================================================================
__global__ __launch_bounds__(256) void phase1_kernel(
    const float* __restrict__ gq, const float* __restrict__ gk,
    const float* __restrict__ gv, const float* __restrict__ gbeta)
{
    extern __shared__ float sm[];
    float* sq    = sm;
    float* sk    = sm + 4224;
    float* sv    = sm + 8448;
    float* sA    = sm + 12672;
    float* sbeta = sm + 13728;
    float* sqs   = sm + 13760;
    float* sks   = sm + 13792;
    float* sAt   = sm + 13824;
    float* stg   = sm + 14848;

    const int t  = threadIdx.x;
    const int ch = blockIdx.x;
    const int bh = blockIdx.y;
    const size_t gbase = ((size_t)bh * LL + (size_t)ch * CC) * 128;

    {
        const float4* q4 = (const float4*)(gq + gbase);
        const float4* k4 = (const float4*)(gk + gbase);
        const float4* v4 = (const float4*)(gv + gbase);
        for (int idx = t; idx < 1024; idx += 256) {
            int r = idx >> 5, c4 = idx & 31;
            ((float4*)(sq + r * SDK))[c4] = q4[idx];
            ((float4*)(sk + r * SDK))[c4] = k4[idx];
            ((float4*)(sv + r * SDK))[c4] = v4[idx];
        }
    }
    if (t < CC) sbeta[t] = gbeta[(size_t)bh * LL + (size_t)ch * CC + t];
    __syncthreads();

    {   // row l2 norms
        int row = t >> 3, seg = t & 7;
        const float4* qr = (const float4*)(sq + row * SDK) + seg * 4;
        const float4* kr = (const float4*)(sk + row * SDK) + seg * 4;
        float s2q = 0.f, s2k = 0.f;
        #pragma unroll
        for (int i2 = 0; i2 < 4; i2++) {
            float4 a = qr[i2]; s2q += dot4(a, a);
            float4 b = kr[i2]; s2k += dot4(b, b);
        }
        #pragma unroll
        for (int off = 4; off; off >>= 1) {
            s2q += __shfl_down_sync(0xffffffffu, s2q, off, 8);
            s2k += __shfl_down_sync(0xffffffffu, s2k, off, 8);
        }
        if (seg == 0) { sqs[row] = rsqrtf(s2q + 1e-6f); sks[row] = rsqrtf(s2k + 1e-6f); }
    }
    __syncthreads();
    {
        int row = t >> 3, seg = t & 7;
        float a = sqs[row], b = sks[row];
        float4* qr = (float4*)(sq + row * SDK) + seg * 4;
        float4* kr = (float4*)(sk + row * SDK) + seg * 4;
        #pragma unroll
        for (int i2 = 0; i2 < 4; i2++) {
            float4 x = qr[i2]; x.x *= a; x.y *= a; x.z *= a; x.w *= a; qr[i2] = x;
            float4 y = kr[i2]; y.x *= b; y.y *= b; y.z *= b; y.w *= b; kr[i2] = y;
        }
    }
    __syncthreads();

    // k-hat row-major -> g_kR (already coalesced)
    const size_t krb = ((size_t)(bh * NCH + ch)) * 4096;
    for (int idx = t; idx < 1024; idx += 256) {
        int r = idx >> 5, c4 = idx & 31;
        *(float4*)(g_kR + krb + (size_t)r * 128 + (c4 << 2)) =
            *(const float4*)(sk + r * SDK + (c4 << 2));
    }

    {   // q-hat (k-major) -> stg cols 32..63 (plain layout)
        int d = t >> 1, half = t & 1, i0q = half * 16;
        #pragma unroll
        for (int ii = 0; ii < 16; ii += 4) {
            float4 a = make_float4(sq[(i0q + ii) * SDK + d], sq[(i0q + ii + 1) * SDK + d],
                                   sq[(i0q + ii + 2) * SDK + d], sq[(i0q + ii + 3) * SDK + d]);
            *(float4*)(stg + d * 64 + 32 + i0q + ii) = a;
        }
    }

    {   // dots (f32x2): A strict-lower -> sA; attn -> sAt (swizzled j4^(i&7))
        int ti = t >> 4, tj = t & 15;
        int i0 = 2 * ti, j0 = 2 * tj;
        ull pkk00 = 0, pkk01 = 0, pkk10 = 0, pkk11 = 0;
        ull pqk00 = 0, pqk01 = 0, pqk10 = 0, pqk11 = 0;
        const ulonglong2* ki0 = (const ulonglong2*)(sk + i0 * SDK);
        const ulonglong2* ki1 = (const ulonglong2*)(sk + (i0 + 1) * SDK);
        const ulonglong2* kj0 = (const ulonglong2*)(sk + j0 * SDK);
        const ulonglong2* kj1 = (const ulonglong2*)(sk + (j0 + 1) * SDK);
        const ulonglong2* qi0 = (const ulonglong2*)(sq + i0 * SDK);
        const ulonglong2* qi1 = (const ulonglong2*)(sq + (i0 + 1) * SDK);
        #pragma unroll 8
        for (int d4 = 0; d4 < 32; d4++) {
            ulonglong2 A0 = ki0[d4], A1 = ki1[d4];
            ulonglong2 B0 = kj0[d4], B1 = kj1[d4];
            ulonglong2 C0 = qi0[d4], C1 = qi1[d4];
            fm2(pkk00, A0.x, B0.x); fm2(pkk00, A0.y, B0.y);
            fm2(pkk01, A0.x, B1.x); fm2(pkk01, A0.y, B1.y);
            fm2(pkk10, A1.x, B0.x); fm2(pkk10, A1.y, B0.y);
            fm2(pkk11, A1.x, B1.x); fm2(pkk11, A1.y, B1.y);
            fm2(pqk00, C0.x, B0.x); fm2(pqk00, C0.y, B0.y);
            fm2(pqk01, C0.x, B1.x); fm2(pqk01, C0.y, B1.y);
            fm2(pqk10, C1.x, B0.x); fm2(pqk10, C1.y, B0.y);
            fm2(pqk11, C1.x, B1.x); fm2(pqk11, C1.y, B1.y);
        }
        float2 e;
        e = upk(pkk00); float dkk00 = e.x + e.y;
        e = upk(pkk01); float dkk01 = e.x + e.y;
        e = upk(pkk10); float dkk10 = e.x + e.y;
        e = upk(pkk11); float dkk11 = e.x + e.y;
        e = upk(pqk00); float dqk00 = e.x + e.y;
        e = upk(pqk01); float dqk01 = e.x + e.y;
        e = upk(pqk10); float dqk10 = e.x + e.y;
        e = upk(pqk11); float dqk11 = e.x + e.y;
        float bi0 = sbeta[i0], bi1 = sbeta[i0 + 1];
        sA[i0 * 33 + j0]           = (i0 > j0)         ? -bi0 * dkk00 : 0.f;
        sA[i0 * 33 + j0 + 1]       = (i0 > j0 + 1)     ? -bi0 * dkk01 : 0.f;
        sA[(i0 + 1) * 33 + j0]     = (i0 + 1 > j0)     ? -bi1 * dkk10 : 0.f;
        sA[(i0 + 1) * 33 + j0 + 1] = (i0 + 1 > j0 + 1) ? -bi1 * dkk11 : 0.f;
        #define ATW(ii, jj, val) sAt[(ii) * 32 + (((((jj) >> 2) ^ ((ii) & 7)) << 2) + ((jj) & 3))] = (val)
        ATW(i0,     j0,     (i0 >= j0)         ? dqk00 : 0.f);
        ATW(i0,     j0 + 1, (i0 >= j0 + 1)     ? dqk01 : 0.f);
        ATW(i0 + 1, j0,     (i0 + 1 >= j0)     ? dqk10 : 0.f);
        ATW(i0 + 1, j0 + 1, (i0 + 1 >= j0 + 1) ? dqk11 : 0.f);
        #undef ATW
    }
    __syncthreads();

    // forward substitution: shuffle-broadcast (same summation order)
    if (t < 32) {
        const int lane = t;
        for (int i = 1; i < CC; i++) {
            float a = sA[i * 33 + lane];
            float f = a;
            for (int k = 1; k < i; k++) {
                float bk = __shfl_sync(0xffffffffu, a, k);
                f += bk * sA[k * 33 + lane];
            }
            __syncwarp();
            if (lane < i) sA[i * 33 + lane] = f;
            __syncwarp();
        }
        sA[lane * 33 + lane] = 1.0f;
    }
    __syncthreads();
    for (int idx = t; idx < 1024; idx += 256) {
        int i = idx >> 5, j = idx & 31;
        sA[i * 33 + j] *= sbeta[j];
    }
    __syncthreads();

    // u = Abeta @ v (registers) ; w = Abeta @ k-hat -> stg cols 0..31
    ulonglong2 u0a = {0,0}, u0b = {0,0}, u1a = {0,0}, u1b = {0,0};
    {
        int p = t >> 4, dseg = t & 15;
        int i0 = 2 * p, d0 = 8 * dseg;
        ulonglong2 w0a = {0,0}, w0b = {0,0}, w1a = {0,0}, w1b = {0,0};
        #pragma unroll 4
        for (int j = 0; j < CC; j++) {
            ull A0 = pk1(sA[i0 * 33 + j]);
            ull A1 = pk1(sA[(i0 + 1) * 33 + j]);
            ulonglong2 va = *(const ulonglong2*)(sv + j * SDK + d0);
            ulonglong2 vb = *(const ulonglong2*)(sv + j * SDK + d0 + 4);
            ulonglong2 ka = *(const ulonglong2*)(sk + j * SDK + d0);
            ulonglong2 kb = *(const ulonglong2*)(sk + j * SDK + d0 + 4);
            fm2(u0a.x, A0, va.x); fm2(u0a.y, A0, va.y);
            fm2(u0b.x, A0, vb.x); fm2(u0b.y, A0, vb.y);
            fm2(u1a.x, A1, va.x); fm2(u1a.y, A1, va.y);
            fm2(u1b.x, A1, vb.x); fm2(u1b.y, A1, vb.y);
            fm2(w0a.x, A0, ka.x); fm2(w0a.y, A0, ka.y);
            fm2(w0b.x, A0, kb.x); fm2(w0b.y, A0, kb.y);
            fm2(w1a.x, A1, ka.x); fm2(w1a.y, A1, ka.y);
            fm2(w1b.x, A1, kb.x); fm2(w1b.y, A1, kb.y);
        }
        float w0arr[8], w1arr[8];
        float2 e;
        e = upk(w0a.x); w0arr[0] = e.x; w0arr[1] = e.y;
        e = upk(w0a.y); w0arr[2] = e.x; w0arr[3] = e.y;
        e = upk(w0b.x); w0arr[4] = e.x; w0arr[5] = e.y;
        e = upk(w0b.y); w0arr[6] = e.x; w0arr[7] = e.y;
        e = upk(w1a.x); w1arr[0] = e.x; w1arr[1] = e.y;
        e = upk(w1a.y); w1arr[2] = e.x; w1arr[3] = e.y;
        e = upk(w1b.x); w1arr[4] = e.x; w1arr[5] = e.y;
        e = upk(w1b.y); w1arr[6] = e.x; w1arr[7] = e.y;
        #pragma unroll
        for (int dd = 0; dd < 8; dd++)
            *(float2*)(stg + (d0 + dd) * 64 + i0) = make_float2(w0arr[dd], w1arr[dd]);
    }
    __syncthreads();   // all sv reads done; w/q fully staged

    // u registers -> sv reused as tight [32][128]
    {
        int p = t >> 4, dseg = t & 15;
        int i0 = 2 * p, d0 = 8 * dseg;
        *(ulonglong2*)(sv + i0 * 128 + d0)           = u0a;
        *(ulonglong2*)(sv + i0 * 128 + d0 + 4)       = u0b;
        *(ulonglong2*)(sv + (i0 + 1) * 128 + d0)     = u1a;
        *(ulonglong2*)(sv + (i0 + 1) * 128 + d0 + 4) = u1b;
    }
    __syncthreads();

    // ---- coalesced copies to global ----
    const size_t wqb = ((size_t)(bh * NCH + ch)) * 8192;
    for (int f4 = t; f4 < 2048; f4 += 256)
        *(float4*)(g_wqT + wqb + ((size_t)f4 << 2)) = *(const float4*)(stg + (f4 << 2));
    {
        size_t ab = ((size_t)(bh * NCH + ch)) * 1024;
        *(float4*)(g_at2 + ab + ((size_t)t << 2)) = *(const float4*)(sAt + (t << 2));
    }
    // u: [32][128] -> 8 slice blocks [32][16], 64B runs per block
    for (int idx = t; idx < 1024; idx += 256) {
        int i = idx >> 5, rem = idx & 31;
        int sl = rem >> 2, c4 = rem & 3;
        size_t ub2 = (((size_t)(bh * 8 + sl)) * NCH + ch) * 512;
        *(float4*)(g_u2 + ub2 + (size_t)i * 16 + (c4 << 2)) =
            *(const float4*)(sv + i * 128 + sl * 16 + (c4 << 2));
    }
}

// =====================================================================
// Phase 2 (unchanged 276us version): grid (8, BHT), 256 threads.
// =====================================================================
#define BUF_F   13824
#define OFF_K   8192
#define OFF_AT  12288
#define OFF_U   13312
#define TX_BYTES 55296u

__global__ __launch_bounds__(256) void phase2_kernel(
    float* __restrict__ out, float* __restrict__ Sout)
{
    extern __shared__ float sm[];
    float* sS   = sm + 4;
    float* po   = sm + 4 + 2048;
    float* bufs = sm + 4 + 2048 + 512;

    const int t = threadIdx.x;
    const int slice = blockIdx.x;
    const int bh    = blockIdx.y;
    const int c0    = slice * 16;

    const int lane = t & 31, warp = t >> 5;
    const int tl = lane & 7, kg = lane >> 3;
    const int tile = warp * 8 + tl;
    const int tr = tile & 15, tc = tile >> 4;
    const int i0 = tr << 2;
    const int cb4 = tc << 2;

    const uint32_t mb0 = s2u(sm), mb1 = mb0 + 8;

    for (int idx = t; idx < 2048; idx += 256) sS[idx] = 0.f;
    if (t == 0) { mbar_init(mb0, 1); mbar_init(mb1, 1); }
    __syncthreads();

    const size_t cb0 = (size_t)bh * NCH;
    const size_t ublk = ((size_t)(bh * 8 + slice)) * NCH;
    if (t == 0) {
        mbar_expect(mb0, TX_BYTES);
        bulkcp(s2u(bufs),           g_wqT + cb0 * 8192, 32768, mb0);
        bulkcp(s2u(bufs + OFF_K),   g_kR  + cb0 * 4096, 16384, mb0);
        bulkcp(s2u(bufs + OFF_AT),  g_at2 + cb0 * 1024, 4096, mb0);
        bulkcp(s2u(bufs + OFF_U),   g_u2  + ublk * 512, 2048, mb0);
    }

    for (int ch = 0; ch < NCH; ch++) {
        const int b = ch & 1;
        float* B  = bufs + b * BUF_F;
        float* bu = B + OFF_U;

        __syncthreads();
        if (t == 0 && ch + 1 < NCH) {
            uint32_t mb = b ? mb0 : mb1;
            float* B2 = bufs + (b ^ 1) * BUF_F;
            const size_t cb = cb0 + ch + 1;
            mbar_expect(mb, TX_BYTES);
            bulkcp(s2u(B2),          g_wqT + cb * 8192, 32768, mb);
            bulkcp(s2u(B2 + OFF_K),  g_kR  + cb * 4096, 16384, mb);
            bulkcp(s2u(B2 + OFF_AT), g_at2 + cb * 1024, 4096, mb);
            bulkcp(s2u(B2 + OFF_U),  g_u2  + (ublk + ch + 1) * 512, 2048, mb);
        }
        mbar_wait(b ? mb1 : mb0, (ch >> 1) & 1);

        ull a00 = 0, a01 = 0, a10 = 0, a11 = 0, a20 = 0, a21 = 0, a30 = 0, a31 = 0;
        {
            const float* wp = B + (kg << 5) * 64 + i0;
            const float* sbase = sS + (kg << 5) * 16;
            #pragma unroll
            for (int k = 0; k < 32; k++) {
                float4 w4 = *(const float4*)(wp + k * 64);
                const int phys = ((tc ^ ((k >> 2) & 3) ^ kg) << 2);
                ulonglong2 s2 = *(const ulonglong2*)(sbase + k * 16 + phys);
                fm2(a00, pk1(w4.x), s2.x); fm2(a01, pk1(w4.x), s2.y);
                fm2(a10, pk1(w4.y), s2.x); fm2(a11, pk1(w4.y), s2.y);
                fm2(a20, pk1(w4.z), s2.x); fm2(a21, pk1(w4.z), s2.y);
                fm2(a30, pk1(w4.w), s2.x); fm2(a31, pk1(w4.w), s2.y);
            }
        }
        #pragma unroll
        for (int m = 8; m <= 16; m <<= 1) {
            a00 = ad2r(a00, __shfl_xor_sync(0xffffffffu, a00, m));
            a01 = ad2r(a01, __shfl_xor_sync(0xffffffffu, a01, m));
            a10 = ad2r(a10, __shfl_xor_sync(0xffffffffu, a10, m));
            a11 = ad2r(a11, __shfl_xor_sync(0xffffffffu, a11, m));
            a20 = ad2r(a20, __shfl_xor_sync(0xffffffffu, a20, m));
            a21 = ad2r(a21, __shfl_xor_sync(0xffffffffu, a21, m));
            a30 = ad2r(a30, __shfl_xor_sync(0xffffffffu, a30, m));
            a31 = ad2r(a31, __shfl_xor_sync(0xffffffffu, a31, m));
        }
        if (kg == 0) {
            float2 l0 = upk(a00), h0 = upk(a01);
            float2 l1 = upk(a10), h1 = upk(a11);
            float2 l2 = upk(a20), h2 = upk(a21);
            float2 l3 = upk(a30), h3 = upk(a31);
            if (tr < 8) {
                float* up = bu + i0 * 16 + cb4;
                float4 u0 = *(const float4*)(up);
                float4 u1 = *(const float4*)(up + 16);
                float4 u2 = *(const float4*)(up + 32);
                float4 u3 = *(const float4*)(up + 48);
                u0.x -= l0.x; u0.y -= l0.y; u0.z -= h0.x; u0.w -= h0.y;
                u1.x -= l1.x; u1.y -= l1.y; u1.z -= h1.x; u1.w -= h1.y;
                u2.x -= l2.x; u2.y -= l2.y; u2.z -= h2.x; u2.w -= h2.y;
                u3.x -= l3.x; u3.y -= l3.y; u3.z -= h3.x; u3.w -= h3.y;
                *(float4*)(up)      = u0;
                *(float4*)(up + 16) = u1;
                *(float4*)(up + 32) = u2;
                *(float4*)(up + 48) = u3;
            } else {
                float* pp = po + (i0 - 32) * 16 + cb4;
                *(float4*)(pp)      = make_float4(l0.x, l0.y, h0.x, h0.y);
                *(float4*)(pp + 16) = make_float4(l1.x, l1.y, h1.x, h1.y);
                *(float4*)(pp + 32) = make_float4(l2.x, l2.y, h2.x, h2.y);
                *(float4*)(pp + 48) = make_float4(l3.x, l3.y, h3.x, h3.y);
            }
        }
        __syncthreads();

        if (t < 128) {
            const int rt = t >> 2, ct = t & 3;
            const int rb = rt << 2;
            const int physc = ((ct ^ ((rt ^ (rt >> 3)) & 3)) << 2);
            float* sp0 = sS + rb * 16 + physc;
            ulonglong2 s0 = *(const ulonglong2*)(sp0);
            ulonglong2 s1 = *(const ulonglong2*)(sp0 + 16);
            ulonglong2 s2v = *(const ulonglong2*)(sp0 + 32);
            ulonglong2 s3 = *(const ulonglong2*)(sp0 + 48);
            const float* kp = B + OFF_K + rb;
            const float* up2 = bu + (ct << 2);
            #pragma unroll 8
            for (int j = 0; j < 32; j++) {
                float4 k4 = *(const float4*)kp;
                ulonglong2 u2 = *(const ulonglong2*)up2;
                fm2(s0.x,  pk1(k4.x), u2.x); fm2(s0.y,  pk1(k4.x), u2.y);
                fm2(s1.x,  pk1(k4.y), u2.x); fm2(s1.y,  pk1(k4.y), u2.y);
                fm2(s2v.x, pk1(k4.z), u2.x); fm2(s2v.y, pk1(k4.z), u2.y);
                fm2(s3.x,  pk1(k4.w), u2.x); fm2(s3.y,  pk1(k4.w), u2.y);
                kp += 128; up2 += 16;
            }
            *(ulonglong2*)(sp0)      = s0;
            *(ulonglong2*)(sp0 + 16) = s1;
            *(ulonglong2*)(sp0 + 32) = s2v;
            *(ulonglong2*)(sp0 + 48) = s3;
        } else {
            const int ii2 = (t - 128) >> 2, cq = t & 3;
            const int asw = ii2 & 7;
            ulonglong2 acc = *(const ulonglong2*)(po + ii2 * 16 + (cq << 2));
            const float* atr = B + OFF_AT + ii2 * 32;
            const float* Up = bu + (cq << 2);
            #pragma unroll
            for (int j4 = 0; j4 < 8; j4++) {
                float4 a4 = *(const float4*)(atr + ((j4 ^ asw) << 2));
                const float* u0p = Up + (j4 << 6);
                ulonglong2 U0 = *(const ulonglong2*)(u0p);
                ulonglong2 U1 = *(const ulonglong2*)(u0p + 16);
                ulonglong2 U2 = *(const ulonglong2*)(u0p + 32);
                ulonglong2 U3 = *(const ulonglong2*)(u0p + 48);
                fm2(acc.x, pk1(a4.x), U0.x); fm2(acc.y, pk1(a4.x), U0.y);
                fm2(acc.x, pk1(a4.y), U1.x); fm2(acc.y, pk1(a4.y), U1.y);
                fm2(acc.x, pk1(a4.z), U2.x); fm2(acc.y, pk1(a4.z), U2.y);
                fm2(acc.x, pk1(a4.w), U3.x); fm2(acc.y, pk1(a4.w), U3.y);
            }
            float2 f0 = upk(acc.x), f1 = upk(acc.y);
            size_t off = ((size_t)bh * LL + (size_t)ch * CC + ii2) * 128 + c0 + (cq << 2);
            *(float4*)(out + off) = make_float4(f0.x, f0.y, f1.x, f1.y);
        }
    }

    if (Sout != nullptr) {
        __syncthreads();
        size_t sb = (size_t)bh * 128 * 128;
        for (int idx = t; idx < 2048; idx += 256) {
            int r = idx >> 4, c = idx & 15;
            int phys = ((((c >> 2) ^ ((r >> 2) & 3) ^ ((r >> 5) & 3)) & 3) << 2) + (c & 3);
            Sout[sb + (size_t)r * 128 + c0 + c] = sS[r * 16 + phys];
        }
    }
}

// =====================================================================
#define P1_SMEM (23040 * (int)sizeof(float))
#define P2_SMEM ((4 + 2048 + 512 + 2 * BUF_F) * (int)sizeof(float))

extern "C" void kernel_launch(void* const* d_in, const int* in_sizes, int n_in,
                              void* d_out, int out_size)
{
    const float* q    = (const float*)d_in[0];
    const float* k    = (const float*)d_in[1];
    const float* v    = (const float*)d_in[2];
    const float* beta = (const float*)d_in[3];
    float* out = (float*)d_out;
    float* Sout = ((size_t)out_size >= OUT_ELEMS + S_ELEMS) ? (out + OUT_ELEMS) : nullptr;

    cudaFuncSetAttribute(phase1_kernel, cudaFuncAttributeMaxDynamicSharedMemorySize, P1_SMEM);
    cudaFuncSetAttribute(phase2_kernel, cudaFuncAttributeMaxDynamicSharedMemorySize, P2_SMEM);

    phase1_kernel<<<dim3(NCH, BHT), 256, P1_SMEM>>>(q, k, v, beta);
    phase2_kernel<<<dim3(8, BHT), 256, P2_SMEM>>>(out, Sout);
}

// round 12
// speedup vs baseline: 1.0899x; 1.0599x over previous
#include <cuda_runtime.h>
#include <cuda_bf16.h>
#include <cstdint>
#include <cstddef>

#define LL   4096
#define CC   32
#define NCH  128
#define BHT  16
#define SDK  132
#define OUT_ELEMS  ((size_t)BHT * LL * 128)
#define S_ELEMS    ((size_t)BHT * 128 * 128)

typedef unsigned long long ull;

// g_wqT: [bh][ch][128][64] k-major: cols 0..31 = w rows, 32..63 = q-hat rows
// g_kR : [bh][ch][32][128] k-hat row-major
// g_at2: [bh][ch][32][32]  masked attn, chunks swizzled (j4 ^ (i&7))
// g_u2 : [bh][slice8][ch][32][16]
__device__ float g_wqT[(size_t)BHT * NCH * 128 * 64];
__device__ float g_kR [(size_t)BHT * NCH * 32 * 128];
__device__ float g_at2[(size_t)BHT * NCH * 32 * 32];
__device__ float g_u2 [(size_t)BHT * 8 * NCH * 32 * 16];

__device__ __forceinline__ float dot4(float4 a, float4 b) {
    return a.x * b.x + a.y * b.y + a.z * b.z + a.w * b.w;
}
__device__ __forceinline__ ull pk1(float x) {
    ull r; asm("mov.b64 %0,{%1,%1};" : "=l"(r) : "f"(x)); return r;
}
__device__ __forceinline__ void fm2(ull& a, ull b, ull c) {
    asm("fma.rn.f32x2 %0,%1,%2,%3;" : "=l"(a) : "l"(b), "l"(c), "l"(a));
}
__device__ __forceinline__ ull ad2r(ull a, ull b) {
    ull r; asm("add.rn.f32x2 %0,%1,%2;" : "=l"(r) : "l"(a), "l"(b)); return r;
}
__device__ __forceinline__ float2 upk(ull a) {
    float2 f; asm("mov.b64 {%0,%1},%2;" : "=f"(f.x), "=f"(f.y) : "l"(a)); return f;
}
__device__ __forceinline__ uint32_t s2u(const void* p) {
    return (uint32_t)__cvta_generic_to_shared(p);
}
__device__ __forceinline__ void mbar_init(uint32_t m, uint32_t c) {
    asm volatile("mbarrier.init.shared.b64 [%0], %1;" :: "r"(m), "r"(c) : "memory");
}
__device__ __forceinline__ void mbar_expect(uint32_t m, uint32_t b) {
    asm volatile("mbarrier.arrive.expect_tx.shared.b64 _, [%0], %1;" :: "r"(m), "r"(b) : "memory");
}
__device__ __forceinline__ void mbar_wait(uint32_t m, uint32_t p) {
    asm volatile(
        "{\n\t.reg .pred P;\n\tW%=:\n\t"
        "mbarrier.try_wait.parity.acquire.cta.shared::cta.b64 P, [%0], %1, 0x989680;\n\t"
        "@P bra D%=;\n\tbra W%=;\n\tD%=:\n\t}" :: "r"(m), "r"(p) : "memory");
}
__device__ __forceinline__ void bulkcp(uint32_t d, const void* s, uint32_t b, uint32_t m) {
    asm volatile("cp.async.bulk.shared::cta.global.mbarrier::complete_tx::bytes [%0], [%1], %2, [%3];"
        :: "r"(d), "l"(s), "r"(b), "r"(m) : "memory");
}

// =====================================================================
// Phase 1: grid (NCH, BHT), 256 threads, min 3 CTAs/SM.
// =====================================================================
__global__ __launch_bounds__(256, 3) void phase1_kernel(
    const float* __restrict__ gq, const float* __restrict__ gk,
    const float* __restrict__ gv, const float* __restrict__ gbeta)
{
    extern __shared__ float sm[];
    float* sq    = sm;
    float* sk    = sm + CC * SDK;
    float* sv    = sm + 2 * CC * SDK;
    float* sA    = sm + 3 * CC * SDK;
    float* sbeta = sA + CC * (CC + 1);
    float* sqs   = sbeta + CC;
    float* sks   = sqs + CC;

    const int t  = threadIdx.x;
    const int ch = blockIdx.x;
    const int bh = blockIdx.y;
    const size_t gbase = ((size_t)bh * LL + (size_t)ch * CC) * 128;

    {
        const float4* q4 = (const float4*)(gq + gbase);
        const float4* k4 = (const float4*)(gk + gbase);
        const float4* v4 = (const float4*)(gv + gbase);
        for (int idx = t; idx < 1024; idx += 256) {
            int r = idx >> 5, c4 = idx & 31;
            ((float4*)(sq + r * SDK))[c4] = q4[idx];
            ((float4*)(sk + r * SDK))[c4] = k4[idx];
            ((float4*)(sv + r * SDK))[c4] = v4[idx];
        }
    }
    if (t < CC) sbeta[t] = gbeta[(size_t)bh * LL + (size_t)ch * CC + t];
    __syncthreads();

    {   // row l2 norms
        int row = t >> 3, seg = t & 7;
        const float4* qr = (const float4*)(sq + row * SDK) + seg * 4;
        const float4* kr = (const float4*)(sk + row * SDK) + seg * 4;
        float s2q = 0.f, s2k = 0.f;
        #pragma unroll
        for (int i2 = 0; i2 < 4; i2++) {
            float4 a = qr[i2]; s2q += dot4(a, a);
            float4 b = kr[i2]; s2k += dot4(b, b);
        }
        #pragma unroll
        for (int off = 4; off; off >>= 1) {
            s2q += __shfl_down_sync(0xffffffffu, s2q, off, 8);
            s2k += __shfl_down_sync(0xffffffffu, s2k, off, 8);
        }
        if (seg == 0) { sqs[row] = rsqrtf(s2q + 1e-6f); sks[row] = rsqrtf(s2k + 1e-6f); }
    }
    __syncthreads();
    {
        int row = t >> 3, seg = t & 7;
        float a = sqs[row], b = sks[row];
        float4* qr = (float4*)(sq + row * SDK) + seg * 4;
        float4* kr = (float4*)(sk + row * SDK) + seg * 4;
        #pragma unroll
        for (int i2 = 0; i2 < 4; i2++) {
            float4 x = qr[i2]; x.x *= a; x.y *= a; x.z *= a; x.w *= a; qr[i2] = x;
            float4 y = kr[i2]; y.x *= b; y.y *= b; y.z *= b; y.w *= b; kr[i2] = y;
        }
    }
    __syncthreads();

    const size_t wqb   = ((size_t)(bh * NCH + ch)) * 8192;
    const size_t krb   = ((size_t)(bh * NCH + ch)) * 4096;
    const size_t abase = ((size_t)(bh * NCH + ch)) * 1024;

    {   // q-hat (k-major) -> g_wqT cols 32..63
        int d = t >> 1, half = t & 1, i0q = half * 16;
        #pragma unroll
        for (int ii = 0; ii < 16; ii += 4) {
            float4 a = make_float4(sq[(i0q + ii) * SDK + d], sq[(i0q + ii + 1) * SDK + d],
                                   sq[(i0q + ii + 2) * SDK + d], sq[(i0q + ii + 3) * SDK + d]);
            *(float4*)(g_wqT + wqb + (size_t)d * 64 + 32 + i0q + ii) = a;
        }
    }
    for (int idx = t; idx < 1024; idx += 256) {
        int r = idx >> 5, c4 = idx & 31;
        *(float4*)(g_kR + krb + (size_t)r * 128 + (c4 << 2)) =
            *(const float4*)(sk + r * SDK + (c4 << 2));
    }

    {   // dots (f32x2)
        int ti = t >> 4, tj = t & 15;
        int i0 = 2 * ti, j0 = 2 * tj;
        ull pkk00 = 0, pkk01 = 0, pkk10 = 0, pkk11 = 0;
        ull pqk00 = 0, pqk01 = 0, pqk10 = 0, pqk11 = 0;
        const ulonglong2* ki0 = (const ulonglong2*)(sk + i0 * SDK);
        const ulonglong2* ki1 = (const ulonglong2*)(sk + (i0 + 1) * SDK);
        const ulonglong2* kj0 = (const ulonglong2*)(sk + j0 * SDK);
        const ulonglong2* kj1 = (const ulonglong2*)(sk + (j0 + 1) * SDK);
        const ulonglong2* qi0 = (const ulonglong2*)(sq + i0 * SDK);
        const ulonglong2* qi1 = (const ulonglong2*)(sq + (i0 + 1) * SDK);
        #pragma unroll 8
        for (int d4 = 0; d4 < 32; d4++) {
            ulonglong2 A0 = ki0[d4], A1 = ki1[d4];
            ulonglong2 B0 = kj0[d4], B1 = kj1[d4];
            ulonglong2 C0 = qi0[d4], C1 = qi1[d4];
            fm2(pkk00, A0.x, B0.x); fm2(pkk00, A0.y, B0.y);
            fm2(pkk01, A0.x, B1.x); fm2(pkk01, A0.y, B1.y);
            fm2(pkk10, A1.x, B0.x); fm2(pkk10, A1.y, B0.y);
            fm2(pkk11, A1.x, B1.x); fm2(pkk11, A1.y, B1.y);
            fm2(pqk00, C0.x, B0.x); fm2(pqk00, C0.y, B0.y);
            fm2(pqk01, C0.x, B1.x); fm2(pqk01, C0.y, B1.y);
            fm2(pqk10, C1.x, B0.x); fm2(pqk10, C1.y, B0.y);
            fm2(pqk11, C1.x, B1.x); fm2(pqk11, C1.y, B1.y);
        }
        float2 e;
        e = upk(pkk00); float dkk00 = e.x + e.y;
        e = upk(pkk01); float dkk01 = e.x + e.y;
        e = upk(pkk10); float dkk10 = e.x + e.y;
        e = upk(pkk11); float dkk11 = e.x + e.y;
        e = upk(pqk00); float dqk00 = e.x + e.y;
        e = upk(pqk01); float dqk01 = e.x + e.y;
        e = upk(pqk10); float dqk10 = e.x + e.y;
        e = upk(pqk11); float dqk11 = e.x + e.y;
        float bi0 = sbeta[i0], bi1 = sbeta[i0 + 1];
        sA[i0 * 33 + j0]           = (i0 > j0)         ? -bi0 * dkk00 : 0.f;
        sA[i0 * 33 + j0 + 1]       = (i0 > j0 + 1)     ? -bi0 * dkk01 : 0.f;
        sA[(i0 + 1) * 33 + j0]     = (i0 + 1 > j0)     ? -bi1 * dkk10 : 0.f;
        sA[(i0 + 1) * 33 + j0 + 1] = (i0 + 1 > j0 + 1) ? -bi1 * dkk11 : 0.f;
        #define ATW(ii, jj, val) g_at2[abase + (size_t)(ii) * 32 + \
            (size_t)(((((jj) >> 2) ^ ((ii) & 7)) << 2) + ((jj) & 3))] = (val)
        ATW(i0,     j0,     (i0 >= j0)         ? dqk00 : 0.f);
        ATW(i0,     j0 + 1, (i0 >= j0 + 1)     ? dqk01 : 0.f);
        ATW(i0 + 1, j0,     (i0 + 1 >= j0)     ? dqk10 : 0.f);
        ATW(i0 + 1, j0 + 1, (i0 + 1 >= j0 + 1) ? dqk11 : 0.f);
        #undef ATW
    }
    __syncthreads();

    // forward substitution (exact reference order), warp 0
    if (t < 32) {
        int lane = t;
        for (int i = 1; i < CC; i++) {
            float s = 0.f;
            if (lane < i) {
                for (int kk = lane + 1; kk < i; kk++)
                    s += sA[i * 33 + kk] * sA[kk * 33 + lane];
            }
            __syncwarp();
            if (lane < i) sA[i * 33 + lane] += s;
            __syncwarp();
        }
        sA[lane * 33 + lane] = 1.0f;
    }
    __syncthreads();

    for (int idx = t; idx < 1024; idx += 256) {
        int i = idx >> 5, j = idx & 31;
        sA[i * 33 + j] *= sbeta[j];
    }
    __syncthreads();

    // u = Abeta @ v ; w = Abeta @ k-hat
    {
        int p = t >> 4, dseg = t & 15;
        int i0 = 2 * p, d0 = 8 * dseg;
        ulonglong2 u0a = {0,0}, u0b = {0,0}, u1a = {0,0}, u1b = {0,0};
        ulonglong2 w0a = {0,0}, w0b = {0,0}, w1a = {0,0}, w1b = {0,0};
        #pragma unroll 4
        for (int j = 0; j < CC; j++) {
            ull A0 = pk1(sA[i0 * 33 + j]);
            ull A1 = pk1(sA[(i0 + 1) * 33 + j]);
            ulonglong2 va = *(const ulonglong2*)(sv + j * SDK + d0);
            ulonglong2 vb = *(const ulonglong2*)(sv + j * SDK + d0 + 4);
            ulonglong2 ka = *(const ulonglong2*)(sk + j * SDK + d0);
            ulonglong2 kb = *(const ulonglong2*)(sk + j * SDK + d0 + 4);
            fm2(u0a.x, A0, va.x); fm2(u0a.y, A0, va.y);
            fm2(u0b.x, A0, vb.x); fm2(u0b.y, A0, vb.y);
            fm2(u1a.x, A1, va.x); fm2(u1a.y, A1, va.y);
            fm2(u1b.x, A1, vb.x); fm2(u1b.y, A1, vb.y);
            fm2(w0a.x, A0, ka.x); fm2(w0a.y, A0, ka.y);
            fm2(w0b.x, A0, kb.x); fm2(w0b.y, A0, kb.y);
            fm2(w1a.x, A1, ka.x); fm2(w1a.y, A1, ka.y);
            fm2(w1b.x, A1, kb.x); fm2(w1b.y, A1, kb.y);
        }
        int sl = d0 >> 4, off = d0 & 15;
        size_t ub2 = (((size_t)(bh * 8 + sl)) * NCH + ch) * 512;
        *(ulonglong2*)(g_u2 + ub2 + (size_t)i0 * 16 + off)           = u0a;
        *(ulonglong2*)(g_u2 + ub2 + (size_t)i0 * 16 + off + 4)       = u0b;
        *(ulonglong2*)(g_u2 + ub2 + (size_t)(i0 + 1) * 16 + off)     = u1a;
        *(ulonglong2*)(g_u2 + ub2 + (size_t)(i0 + 1) * 16 + off + 4) = u1b;
        float w0arr[8], w1arr[8];
        float2 e;
        e = upk(w0a.x); w0arr[0] = e.x; w0arr[1] = e.y;
        e = upk(w0a.y); w0arr[2] = e.x; w0arr[3] = e.y;
        e = upk(w0b.x); w0arr[4] = e.x; w0arr[5] = e.y;
        e = upk(w0b.y); w0arr[6] = e.x; w0arr[7] = e.y;
        e = upk(w1a.x); w1arr[0] = e.x; w1arr[1] = e.y;
        e = upk(w1a.y); w1arr[2] = e.x; w1arr[3] = e.y;
        e = upk(w1b.x); w1arr[4] = e.x; w1arr[5] = e.y;
        e = upk(w1b.y); w1arr[6] = e.x; w1arr[7] = e.y;
        #pragma unroll
        for (int dd = 0; dd < 8; dd++) {
            *(float2*)(g_wqT + wqb + (size_t)(d0 + dd) * 64 + i0) =
                make_float2(w0arr[dd], w1arr[dd]);
        }
    }
}

// =====================================================================
// Phase 2: sequential scan, dv split 8x16. grid (8, BHT), 256 threads.
// Tail (u'/po writes) now distributed across kg lanes.
// =====================================================================
#define BUF_F   13824
#define OFF_K   8192
#define OFF_AT  12288
#define OFF_U   13312
#define TX_BYTES 55296u

__global__ __launch_bounds__(256) void phase2_kernel(
    float* __restrict__ out, float* __restrict__ Sout)
{
    extern __shared__ float sm[];
    float* sS   = sm + 4;
    float* po   = sm + 4 + 2048;
    float* bufs = sm + 4 + 2048 + 512;

    const int t = threadIdx.x;
    const int slice = blockIdx.x;
    const int bh    = blockIdx.y;
    const int c0    = slice * 16;

    const int lane = t & 31, warp = t >> 5;
    const int tl = lane & 7, kg = lane >> 3;
    const int tile = warp * 8 + tl;
    const int tr = tile & 15, tc = tile >> 4;
    const int i0 = tr << 2;
    const int cb4 = tc << 2;

    const uint32_t mb0 = s2u(sm), mb1 = mb0 + 8;

    for (int idx = t; idx < 2048; idx += 256) sS[idx] = 0.f;
    if (t == 0) { mbar_init(mb0, 1); mbar_init(mb1, 1); }
    __syncthreads();

    const size_t cb0 = (size_t)bh * NCH;
    const size_t ublk = ((size_t)(bh * 8 + slice)) * NCH;
    if (t == 0) {
        mbar_expect(mb0, TX_BYTES);
        bulkcp(s2u(bufs),           g_wqT + cb0 * 8192, 32768, mb0);
        bulkcp(s2u(bufs + OFF_K),   g_kR  + cb0 * 4096, 16384, mb0);
        bulkcp(s2u(bufs + OFF_AT),  g_at2 + cb0 * 1024, 4096, mb0);
        bulkcp(s2u(bufs + OFF_U),   g_u2  + ublk * 512, 2048, mb0);
    }

    for (int ch = 0; ch < NCH; ch++) {
        const int b = ch & 1;
        float* B  = bufs + b * BUF_F;
        float* bu = B + OFF_U;

        __syncthreads();
        if (t == 0 && ch + 1 < NCH) {
            uint32_t mb = b ? mb0 : mb1;
            float* B2 = bufs + (b ^ 1) * BUF_F;
            const size_t cb = cb0 + ch + 1;
            mbar_expect(mb, TX_BYTES);
            bulkcp(s2u(B2),          g_wqT + cb * 8192, 32768, mb);
            bulkcp(s2u(B2 + OFF_K),  g_kR  + cb * 4096, 16384, mb);
            bulkcp(s2u(B2 + OFF_AT), g_at2 + cb * 1024, 4096, mb);
            bulkcp(s2u(B2 + OFF_U),  g_u2  + (ublk + ch + 1) * 512, 2048, mb);
        }
        mbar_wait(b ? mb1 : mb0, (ch >> 1) & 1);

        // ---- P = [w;q]@S : 4x4 tile, k-split-4 ----
        ull a00 = 0, a01 = 0, a10 = 0, a11 = 0, a20 = 0, a21 = 0, a30 = 0, a31 = 0;
        {
            const float* wp = B + (kg << 5) * 64 + i0;
            const float* sbase = sS + (kg << 5) * 16;
            #pragma unroll
            for (int k = 0; k < 32; k++) {
                float4 w4 = *(const float4*)(wp + k * 64);
                const int phys = ((tc ^ ((k >> 2) & 3) ^ kg) << 2);
                ulonglong2 s2 = *(const ulonglong2*)(sbase + k * 16 + phys);
                fm2(a00, pk1(w4.x), s2.x); fm2(a01, pk1(w4.x), s2.y);
                fm2(a10, pk1(w4.y), s2.x); fm2(a11, pk1(w4.y), s2.y);
                fm2(a20, pk1(w4.z), s2.x); fm2(a21, pk1(w4.z), s2.y);
                fm2(a30, pk1(w4.w), s2.x); fm2(a31, pk1(w4.w), s2.y);
            }
        }
        #pragma unroll
        for (int m = 8; m <= 16; m <<= 1) {
            a00 = ad2r(a00, __shfl_xor_sync(0xffffffffu, a00, m));
            a01 = ad2r(a01, __shfl_xor_sync(0xffffffffu, a01, m));
            a10 = ad2r(a10, __shfl_xor_sync(0xffffffffu, a10, m));
            a11 = ad2r(a11, __shfl_xor_sync(0xffffffffu, a11, m));
            a20 = ad2r(a20, __shfl_xor_sync(0xffffffffu, a20, m));
            a21 = ad2r(a21, __shfl_xor_sync(0xffffffffu, a21, m));
            a30 = ad2r(a30, __shfl_xor_sync(0xffffffffu, a30, m));
            a31 = ad2r(a31, __shfl_xor_sync(0xffffffffu, a31, m));
        }
        {   // distributed tail: lane kg handles row i0+kg
            ull ax, ay;
            if (kg == 0)      { ax = a00; ay = a01; }
            else if (kg == 1) { ax = a10; ay = a11; }
            else if (kg == 2) { ax = a20; ay = a21; }
            else              { ax = a30; ay = a31; }
            float2 lo = upk(ax), hi = upk(ay);
            const int row = i0 + kg;
            if (tr < 8) {
                float* up = bu + row * 16 + cb4;
                float4 u0 = *(const float4*)up;
                u0.x -= lo.x; u0.y -= lo.y; u0.z -= hi.x; u0.w -= hi.y;
                *(float4*)up = u0;
            } else {
                *(float4*)(po + (row - 32) * 16 + cb4) =
                    make_float4(lo.x, lo.y, hi.x, hi.y);
            }
        }
        __syncthreads();

        if (t < 128) {
            const int rt = t >> 2, ct = t & 3;
            const int rb = rt << 2;
            const int physc = ((ct ^ ((rt ^ (rt >> 3)) & 3)) << 2);
            float* sp0 = sS + rb * 16 + physc;
            ulonglong2 s0 = *(const ulonglong2*)(sp0);
            ulonglong2 s1 = *(const ulonglong2*)(sp0 + 16);
            ulonglong2 s2v = *(const ulonglong2*)(sp0 + 32);
            ulonglong2 s3 = *(const ulonglong2*)(sp0 + 48);
            const float* kp = B + OFF_K + rb;
            const float* up2 = bu + (ct << 2);
            #pragma unroll 8
            for (int j = 0; j < 32; j++) {
                float4 k4 = *(const float4*)kp;
                ulonglong2 u2 = *(const ulonglong2*)up2;
                fm2(s0.x,  pk1(k4.x), u2.x); fm2(s0.y,  pk1(k4.x), u2.y);
                fm2(s1.x,  pk1(k4.y), u2.x); fm2(s1.y,  pk1(k4.y), u2.y);
                fm2(s2v.x, pk1(k4.z), u2.x); fm2(s2v.y, pk1(k4.z), u2.y);
                fm2(s3.x,  pk1(k4.w), u2.x); fm2(s3.y,  pk1(k4.w), u2.y);
                kp += 128; up2 += 16;
            }
            *(ulonglong2*)(sp0)      = s0;
            *(ulonglong2*)(sp0 + 16) = s1;
            *(ulonglong2*)(sp0 + 32) = s2v;
            *(ulonglong2*)(sp0 + 48) = s3;
        } else {
            const int ii2 = (t - 128) >> 2, cq = t & 3;
            const int asw = ii2 & 7;
            ulonglong2 acc = *(const ulonglong2*)(po + ii2 * 16 + (cq << 2));
            const float* atr = B + OFF_AT + ii2 * 32;
            const float* Up = bu + (cq << 2);
            #pragma unroll
            for (int j4 = 0; j4 < 8; j4++) {
                float4 a4 = *(const float4*)(atr + ((j4 ^ asw) << 2));
                const float* u0p = Up + (j4 << 6);
                ulonglong2 U0 = *(const ulonglong2*)(u0p);
                ulonglong2 U1 = *(const ulonglong2*)(u0p + 16);
                ulonglong2 U2 = *(const ulonglong2*)(u0p + 32);
                ulonglong2 U3 = *(const ulonglong2*)(u0p + 48);
                fm2(acc.x, pk1(a4.x), U0.x); fm2(acc.y, pk1(a4.x), U0.y);
                fm2(acc.x, pk1(a4.y), U1.x); fm2(acc.y, pk1(a4.y), U1.y);
                fm2(acc.x, pk1(a4.z), U2.x); fm2(acc.y, pk1(a4.z), U2.y);
                fm2(acc.x, pk1(a4.w), U3.x); fm2(acc.y, pk1(a4.w), U3.y);
            }
            float2 f0 = upk(acc.x), f1 = upk(acc.y);
            size_t off = ((size_t)bh * LL + (size_t)ch * CC + ii2) * 128 + c0 + (cq << 2);
            *(float4*)(out + off) = make_float4(f0.x, f0.y, f1.x, f1.y);
        }
    }

    if (Sout != nullptr) {
        __syncthreads();
        size_t sb = (size_t)bh * 128 * 128;
        for (int idx = t; idx < 2048; idx += 256) {
            int r = idx >> 4, c = idx & 15;
            int phys = ((((c >> 2) ^ ((r >> 2) & 3) ^ ((r >> 5) & 3)) & 3) << 2) + (c & 3);
            Sout[sb + (size_t)r * 128 + c0 + c] = sS[r * 16 + phys];
        }
    }
}

// =====================================================================
#define P1_SMEM ((3 * CC * SDK + CC * (CC + 1) + 3 * CC) * (int)sizeof(float))
#define P2_SMEM ((4 + 2048 + 512 + 2 * BUF_F) * (int)sizeof(float))

extern "C" void kernel_launch(void* const* d_in, const int* in_sizes, int n_in,
                              void* d_out, int out_size)
{
    const float* q    = (const float*)d_in[0];
    const float* k    = (const float*)d_in[1];
    const float* v    = (const float*)d_in[2];
    const float* beta = (const float*)d_in[3];
    float* out = (float*)d_out;
    float* Sout = ((size_t)out_size >= OUT_ELEMS + S_ELEMS) ? (out + OUT_ELEMS) : nullptr;

    cudaFuncSetAttribute(phase1_kernel, cudaFuncAttributeMaxDynamicSharedMemorySize, P1_SMEM);
    cudaFuncSetAttribute(phase2_kernel, cudaFuncAttributeMaxDynamicSharedMemorySize, P2_SMEM);

    phase1_kernel<<<dim3(NCH, BHT), 256, P1_SMEM>>>(q, k, v, beta);
    phase2_kernel<<<dim3(8, BHT), 256, P2_SMEM>>>(out, Sout);
}

// round 13
// speedup vs baseline: 1.1623x; 1.0664x over previous
#include <cuda_runtime.h>
#include <cuda_bf16.h>
#include <cstdint>
#include <cstddef>

#define LL   4096
#define CC   32
#define NCH  128
#define BHT  16
#define SDK  132
#define OUT_ELEMS  ((size_t)BHT * LL * 128)
#define S_ELEMS    ((size_t)BHT * 128 * 128)

typedef unsigned long long ull;

// g_wqT: [bh][ch][128][64] k-major: cols 0..31 = w rows, 32..63 = q-hat rows
// g_kR : [bh][ch][32][128] k-hat row-major
// g_at2: [bh][ch][32][32]  masked attn, chunks swizzled (j4 ^ (i&7))
// g_u2 : [bh][slice8][ch][32][16]
__device__ float g_wqT[(size_t)BHT * NCH * 128 * 64];
__device__ float g_kR [(size_t)BHT * NCH * 32 * 128];
__device__ float g_at2[(size_t)BHT * NCH * 32 * 32];
__device__ float g_u2 [(size_t)BHT * 8 * NCH * 32 * 16];

__device__ __forceinline__ float dot4(float4 a, float4 b) {
    return a.x * b.x + a.y * b.y + a.z * b.z + a.w * b.w;
}
__device__ __forceinline__ ull pk1(float x) {
    ull r; asm("mov.b64 %0,{%1,%1};" : "=l"(r) : "f"(x)); return r;
}
__device__ __forceinline__ void fm2(ull& a, ull b, ull c) {
    asm("fma.rn.f32x2 %0,%1,%2,%3;" : "=l"(a) : "l"(b), "l"(c), "l"(a));
}
__device__ __forceinline__ ull ad2r(ull a, ull b) {
    ull r; asm("add.rn.f32x2 %0,%1,%2;" : "=l"(r) : "l"(a), "l"(b)); return r;
}
__device__ __forceinline__ float2 upk(ull a) {
    float2 f; asm("mov.b64 {%0,%1},%2;" : "=f"(f.x), "=f"(f.y) : "l"(a)); return f;
}
__device__ __forceinline__ uint32_t s2u(const void* p) {
    return (uint32_t)__cvta_generic_to_shared(p);
}
__device__ __forceinline__ void mbar_init(uint32_t m, uint32_t c) {
    asm volatile("mbarrier.init.shared.b64 [%0], %1;" :: "r"(m), "r"(c) : "memory");
}
__device__ __forceinline__ void mbar_expect(uint32_t m, uint32_t b) {
    asm volatile("mbarrier.arrive.expect_tx.shared.b64 _, [%0], %1;" :: "r"(m), "r"(b) : "memory");
}
__device__ __forceinline__ void mbar_wait(uint32_t m, uint32_t p) {
    asm volatile(
        "{\n\t.reg .pred P;\n\tW%=:\n\t"
        "mbarrier.try_wait.parity.acquire.cta.shared::cta.b64 P, [%0], %1, 0x989680;\n\t"
        "@P bra D%=;\n\tbra W%=;\n\tD%=:\n\t}" :: "r"(m), "r"(p) : "memory");
}
__device__ __forceinline__ void bulkcp(uint32_t d, const void* s, uint32_t b, uint32_t m) {
    asm volatile("cp.async.bulk.shared::cta.global.mbarrier::complete_tx::bytes [%0], [%1], %2, [%3];"
        :: "r"(d), "l"(s), "r"(b), "r"(m) : "memory");
}

// =====================================================================
// Phase 1: grid (NCH, BHT), 256 threads.
// =====================================================================
__global__ __launch_bounds__(256) void phase1_kernel(
    const float* __restrict__ gq, const float* __restrict__ gk,
    const float* __restrict__ gv, const float* __restrict__ gbeta)
{
    extern __shared__ float sm[];
    float* sq    = sm;
    float* sk    = sm + CC * SDK;
    float* sv    = sm + 2 * CC * SDK;
    float* sA    = sm + 3 * CC * SDK;
    float* sbeta = sA + CC * (CC + 1);
    float* sqs   = sbeta + CC;
    float* sks   = sqs + CC;

    const int t  = threadIdx.x;
    const int ch = blockIdx.x;
    const int bh = blockIdx.y;
    const size_t gbase = ((size_t)bh * LL + (size_t)ch * CC) * 128;

    {
        const float4* q4 = (const float4*)(gq + gbase);
        const float4* k4 = (const float4*)(gk + gbase);
        const float4* v4 = (const float4*)(gv + gbase);
        for (int idx = t; idx < 1024; idx += 256) {
            int r = idx >> 5, c4 = idx & 31;
            ((float4*)(sq + r * SDK))[c4] = q4[idx];
            ((float4*)(sk + r * SDK))[c4] = k4[idx];
            ((float4*)(sv + r * SDK))[c4] = v4[idx];
        }
    }
    if (t < CC) sbeta[t] = gbeta[(size_t)bh * LL + (size_t)ch * CC + t];
    __syncthreads();

    {   // row l2 norms
        int row = t >> 3, seg = t & 7;
        const float4* qr = (const float4*)(sq + row * SDK) + seg * 4;
        const float4* kr = (const float4*)(sk + row * SDK) + seg * 4;
        float s2q = 0.f, s2k = 0.f;
        #pragma unroll
        for (int i2 = 0; i2 < 4; i2++) {
            float4 a = qr[i2]; s2q += dot4(a, a);
            float4 b = kr[i2]; s2k += dot4(b, b);
        }
        #pragma unroll
        for (int off = 4; off; off >>= 1) {
            s2q += __shfl_down_sync(0xffffffffu, s2q, off, 8);
            s2k += __shfl_down_sync(0xffffffffu, s2k, off, 8);
        }
        if (seg == 0) { sqs[row] = rsqrtf(s2q + 1e-6f); sks[row] = rsqrtf(s2k + 1e-6f); }
    }
    __syncthreads();
    {
        int row = t >> 3, seg = t & 7;
        float a = sqs[row], b = sks[row];
        float4* qr = (float4*)(sq + row * SDK) + seg * 4;
        float4* kr = (float4*)(sk + row * SDK) + seg * 4;
        #pragma unroll
        for (int i2 = 0; i2 < 4; i2++) {
            float4 x = qr[i2]; x.x *= a; x.y *= a; x.z *= a; x.w *= a; qr[i2] = x;
            float4 y = kr[i2]; y.x *= b; y.y *= b; y.z *= b; y.w *= b; kr[i2] = y;
        }
    }
    __syncthreads();

    const size_t wqb   = ((size_t)(bh * NCH + ch)) * 8192;
    const size_t krb   = ((size_t)(bh * NCH + ch)) * 4096;
    const size_t abase = ((size_t)(bh * NCH + ch)) * 1024;

    {   // q-hat (k-major) -> g_wqT cols 32..63
        int d = t >> 1, half = t & 1, i0q = half * 16;
        #pragma unroll
        for (int ii = 0; ii < 16; ii += 4) {
            float4 a = make_float4(sq[(i0q + ii) * SDK + d], sq[(i0q + ii + 1) * SDK + d],
                                   sq[(i0q + ii + 2) * SDK + d], sq[(i0q + ii + 3) * SDK + d]);
            *(float4*)(g_wqT + wqb + (size_t)d * 64 + 32 + i0q + ii) = a;
        }
    }
    for (int idx = t; idx < 1024; idx += 256) {
        int r = idx >> 5, c4 = idx & 31;
        *(float4*)(g_kR + krb + (size_t)r * 128 + (c4 << 2)) =
            *(const float4*)(sk + r * SDK + (c4 << 2));
    }

    {   // dots (f32x2)
        int ti = t >> 4, tj = t & 15;
        int i0 = 2 * ti, j0 = 2 * tj;
        ull pkk00 = 0, pkk01 = 0, pkk10 = 0, pkk11 = 0;
        ull pqk00 = 0, pqk01 = 0, pqk10 = 0, pqk11 = 0;
        const ulonglong2* ki0 = (const ulonglong2*)(sk + i0 * SDK);
        const ulonglong2* ki1 = (const ulonglong2*)(sk + (i0 + 1) * SDK);
        const ulonglong2* kj0 = (const ulonglong2*)(sk + j0 * SDK);
        const ulonglong2* kj1 = (const ulonglong2*)(sk + (j0 + 1) * SDK);
        const ulonglong2* qi0 = (const ulonglong2*)(sq + i0 * SDK);
        const ulonglong2* qi1 = (const ulonglong2*)(sq + (i0 + 1) * SDK);
        #pragma unroll 8
        for (int d4 = 0; d4 < 32; d4++) {
            ulonglong2 A0 = ki0[d4], A1 = ki1[d4];
            ulonglong2 B0 = kj0[d4], B1 = kj1[d4];
            ulonglong2 C0 = qi0[d4], C1 = qi1[d4];
            fm2(pkk00, A0.x, B0.x); fm2(pkk00, A0.y, B0.y);
            fm2(pkk01, A0.x, B1.x); fm2(pkk01, A0.y, B1.y);
            fm2(pkk10, A1.x, B0.x); fm2(pkk10, A1.y, B0.y);
            fm2(pkk11, A1.x, B1.x); fm2(pkk11, A1.y, B1.y);
            fm2(pqk00, C0.x, B0.x); fm2(pqk00, C0.y, B0.y);
            fm2(pqk01, C0.x, B1.x); fm2(pqk01, C0.y, B1.y);
            fm2(pqk10, C1.x, B0.x); fm2(pqk10, C1.y, B0.y);
            fm2(pqk11, C1.x, B1.x); fm2(pqk11, C1.y, B1.y);
        }
        float2 e;
        e = upk(pkk00); float dkk00 = e.x + e.y;
        e = upk(pkk01); float dkk01 = e.x + e.y;
        e = upk(pkk10); float dkk10 = e.x + e.y;
        e = upk(pkk11); float dkk11 = e.x + e.y;
        e = upk(pqk00); float dqk00 = e.x + e.y;
        e = upk(pqk01); float dqk01 = e.x + e.y;
        e = upk(pqk10); float dqk10 = e.x + e.y;
        e = upk(pqk11); float dqk11 = e.x + e.y;
        float bi0 = sbeta[i0], bi1 = sbeta[i0 + 1];
        sA[i0 * 33 + j0]           = (i0 > j0)         ? -bi0 * dkk00 : 0.f;
        sA[i0 * 33 + j0 + 1]       = (i0 > j0 + 1)     ? -bi0 * dkk01 : 0.f;
        sA[(i0 + 1) * 33 + j0]     = (i0 + 1 > j0)     ? -bi1 * dkk10 : 0.f;
        sA[(i0 + 1) * 33 + j0 + 1] = (i0 + 1 > j0 + 1) ? -bi1 * dkk11 : 0.f;
        #define ATW(ii, jj, val) g_at2[abase + (size_t)(ii) * 32 + \
            (size_t)(((((jj) >> 2) ^ ((ii) & 7)) << 2) + ((jj) & 3))] = (val)
        ATW(i0,     j0,     (i0 >= j0)         ? dqk00 : 0.f);
        ATW(i0,     j0 + 1, (i0 >= j0 + 1)     ? dqk01 : 0.f);
        ATW(i0 + 1, j0,     (i0 + 1 >= j0)     ? dqk10 : 0.f);
        ATW(i0 + 1, j0 + 1, (i0 + 1 >= j0 + 1) ? dqk11 : 0.f);
        #undef ATW
    }
    __syncthreads();

    // forward substitution (exact reference order), warp 0
    if (t < 32) {
        int lane = t;
        for (int i = 1; i < CC; i++) {
            float s = 0.f;
            if (lane < i) {
                for (int kk = lane + 1; kk < i; kk++)
                    s += sA[i * 33 + kk] * sA[kk * 33 + lane];
            }
            __syncwarp();
            if (lane < i) sA[i * 33 + lane] += s;
            __syncwarp();
        }
        sA[lane * 33 + lane] = 1.0f;
    }
    __syncthreads();

    for (int idx = t; idx < 1024; idx += 256) {
        int i = idx >> 5, j = idx & 31;
        sA[i * 33 + j] *= sbeta[j];
    }
    __syncthreads();

    // u = Abeta @ v ; w = Abeta @ k-hat
    // Each thread: rows i0,i0+1 x cols {cA..cA+3} and {cB..cB+3}.
    // 16B lane stride -> conflict-floor LDS reads (2 wf/load).
    {
        int p = t >> 4, dseg = t & 15;
        int i0 = 2 * p;
        int cA = dseg << 2;
        int cB = 64 + (dseg << 2);
        ulonglong2 u0a = {0,0}, u0b = {0,0}, u1a = {0,0}, u1b = {0,0};
        ulonglong2 w0a = {0,0}, w0b = {0,0}, w1a = {0,0}, w1b = {0,0};
        #pragma unroll 4
        for (int j = 0; j < CC; j++) {
            ull A0 = pk1(sA[i0 * 33 + j]);
            ull A1 = pk1(sA[(i0 + 1) * 33 + j]);
            ulonglong2 va = *(const ulonglong2*)(sv + j * SDK + cA);
            ulonglong2 vb = *(const ulonglong2*)(sv + j * SDK + cB);
            ulonglong2 ka = *(const ulonglong2*)(sk + j * SDK + cA);
            ulonglong2 kb = *(const ulonglong2*)(sk + j * SDK + cB);
            fm2(u0a.x, A0, va.x); fm2(u0a.y, A0, va.y);
            fm2(u0b.x, A0, vb.x); fm2(u0b.y, A0, vb.y);
            fm2(u1a.x, A1, va.x); fm2(u1a.y, A1, va.y);
            fm2(u1b.x, A1, vb.x); fm2(u1b.y, A1, vb.y);
            fm2(w0a.x, A0, ka.x); fm2(w0a.y, A0, ka.y);
            fm2(w0b.x, A0, kb.x); fm2(w0b.y, A0, kb.y);
            fm2(w1a.x, A1, ka.x); fm2(w1a.y, A1, ka.y);
            fm2(w1b.x, A1, kb.x); fm2(w1b.y, A1, kb.y);
        }
        // u stores: slice A = cA/16, slice B = 4 + cA/16, offset = cA mod 16
        int slA = dseg >> 2, offA = (dseg & 3) << 2;
        size_t ubA = (((size_t)(bh * 8 + slA)) * NCH + ch) * 512;
        size_t ubB = (((size_t)(bh * 8 + 4 + slA)) * NCH + ch) * 512;
        *(ulonglong2*)(g_u2 + ubA + (size_t)i0 * 16 + offA)       = u0a;
        *(ulonglong2*)(g_u2 + ubB + (size_t)i0 * 16 + offA)       = u0b;
        *(ulonglong2*)(g_u2 + ubA + (size_t)(i0 + 1) * 16 + offA) = u1a;
        *(ulonglong2*)(g_u2 + ubB + (size_t)(i0 + 1) * 16 + offA) = u1b;
        // w stores (k-major cols 0..31 of g_wqT): dims cA..cA+3 and cB..cB+3
        float wA0[4], wB0[4], wA1[4], wB1[4];
        float2 e;
        e = upk(w0a.x); wA0[0] = e.x; wA0[1] = e.y;
        e = upk(w0a.y); wA0[2] = e.x; wA0[3] = e.y;
        e = upk(w0b.x); wB0[0] = e.x; wB0[1] = e.y;
        e = upk(w0b.y); wB0[2] = e.x; wB0[3] = e.y;
        e = upk(w1a.x); wA1[0] = e.x; wA1[1] = e.y;
        e = upk(w1a.y); wA1[2] = e.x; wA1[3] = e.y;
        e = upk(w1b.x); wB1[0] = e.x; wB1[1] = e.y;
        e = upk(w1b.y); wB1[2] = e.x; wB1[3] = e.y;
        #pragma unroll
        for (int dd = 0; dd < 4; dd++) {
            *(float2*)(g_wqT + wqb + (size_t)(cA + dd) * 64 + i0) =
                make_float2(wA0[dd], wA1[dd]);
            *(float2*)(g_wqT + wqb + (size_t)(cB + dd) * 64 + i0) =
                make_float2(wB0[dd], wB1[dd]);
        }
    }
}

// =====================================================================
// Phase 2: sequential scan, dv split 8x16. grid (8, BHT), 256 threads.
// =====================================================================
#define BUF_F   13824
#define OFF_K   8192
#define OFF_AT  12288
#define OFF_U   13312
#define TX_BYTES 55296u

__global__ __launch_bounds__(256) void phase2_kernel(
    float* __restrict__ out, float* __restrict__ Sout)
{
    extern __shared__ float sm[];
    float* sS   = sm + 4;
    float* po   = sm + 4 + 2048;
    float* bufs = sm + 4 + 2048 + 512;

    const int t = threadIdx.x;
    const int slice = blockIdx.x;
    const int bh    = blockIdx.y;
    const int c0    = slice * 16;

    const int lane = t & 31, warp = t >> 5;
    const int tl = lane & 7, kg = lane >> 3;
    const int tile = warp * 8 + tl;
    const int tr = tile & 15, tc = tile >> 4;
    const int i0 = tr << 2;
    const int cb4 = tc << 2;

    const uint32_t mb0 = s2u(sm), mb1 = mb0 + 8;

    for (int idx = t; idx < 2048; idx += 256) sS[idx] = 0.f;
    if (t == 0) { mbar_init(mb0, 1); mbar_init(mb1, 1); }
    __syncthreads();

    const size_t cb0 = (size_t)bh * NCH;
    const size_t ublk = ((size_t)(bh * 8 + slice)) * NCH;
    if (t == 0) {
        mbar_expect(mb0, TX_BYTES);
        bulkcp(s2u(bufs),           g_wqT + cb0 * 8192, 32768, mb0);
        bulkcp(s2u(bufs + OFF_K),   g_kR  + cb0 * 4096, 16384, mb0);
        bulkcp(s2u(bufs + OFF_AT),  g_at2 + cb0 * 1024, 4096, mb0);
        bulkcp(s2u(bufs + OFF_U),   g_u2  + ublk * 512, 2048, mb0);
    }

    for (int ch = 0; ch < NCH; ch++) {
        const int b = ch & 1;
        float* B  = bufs + b * BUF_F;
        float* bu = B + OFF_U;

        __syncthreads();
        if (t == 0 && ch + 1 < NCH) {
            uint32_t mb = b ? mb0 : mb1;
            float* B2 = bufs + (b ^ 1) * BUF_F;
            const size_t cb = cb0 + ch + 1;
            mbar_expect(mb, TX_BYTES);
            bulkcp(s2u(B2),          g_wqT + cb * 8192, 32768, mb);
            bulkcp(s2u(B2 + OFF_K),  g_kR  + cb * 4096, 16384, mb);
            bulkcp(s2u(B2 + OFF_AT), g_at2 + cb * 1024, 4096, mb);
            bulkcp(s2u(B2 + OFF_U),  g_u2  + (ublk + ch + 1) * 512, 2048, mb);
        }
        mbar_wait(b ? mb1 : mb0, (ch >> 1) & 1);

        // ---- P = [w;q]@S : 4x4 tile, k-split-4 ----
        ull a00 = 0, a01 = 0, a10 = 0, a11 = 0, a20 = 0, a21 = 0, a30 = 0, a31 = 0;
        {
            const float* wp = B + (kg << 5) * 64 + i0;
            const float* sbase = sS + (kg << 5) * 16;
            #pragma unroll
            for (int k = 0; k < 32; k++) {
                float4 w4 = *(const float4*)(wp + k * 64);
                const int phys = ((tc ^ ((k >> 2) & 3) ^ kg) << 2);
                ulonglong2 s2 = *(const ulonglong2*)(sbase + k * 16 + phys);
                fm2(a00, pk1(w4.x), s2.x); fm2(a01, pk1(w4.x), s2.y);
                fm2(a10, pk1(w4.y), s2.x); fm2(a11, pk1(w4.y), s2.y);
                fm2(a20, pk1(w4.z), s2.x); fm2(a21, pk1(w4.z), s2.y);
                fm2(a30, pk1(w4.w), s2.x); fm2(a31, pk1(w4.w), s2.y);
            }
        }
        #pragma unroll
        for (int m = 8; m <= 16; m <<= 1) {
            a00 = ad2r(a00, __shfl_xor_sync(0xffffffffu, a00, m));
            a01 = ad2r(a01, __shfl_xor_sync(0xffffffffu, a01, m));
            a10 = ad2r(a10, __shfl_xor_sync(0xffffffffu, a10, m));
            a11 = ad2r(a11, __shfl_xor_sync(0xffffffffu, a11, m));
            a20 = ad2r(a20, __shfl_xor_sync(0xffffffffu, a20, m));
            a21 = ad2r(a21, __shfl_xor_sync(0xffffffffu, a21, m));
            a30 = ad2r(a30, __shfl_xor_sync(0xffffffffu, a30, m));
            a31 = ad2r(a31, __shfl_xor_sync(0xffffffffu, a31, m));
        }
        {   // distributed tail: lane kg handles row i0+kg
            ull ax, ay;
            if (kg == 0)      { ax = a00; ay = a01; }
            else if (kg == 1) { ax = a10; ay = a11; }
            else if (kg == 2) { ax = a20; ay = a21; }
            else              { ax = a30; ay = a31; }
            float2 lo = upk(ax), hi = upk(ay);
            const int row = i0 + kg;
            if (tr < 8) {
                float* up = bu + row * 16 + cb4;
                float4 u0 = *(const float4*)up;
                u0.x -= lo.x; u0.y -= lo.y; u0.z -= hi.x; u0.w -= hi.y;
                *(float4*)up = u0;
            } else {
                *(float4*)(po + (row - 32) * 16 + cb4) =
                    make_float4(lo.x, lo.y, hi.x, hi.y);
            }
        }
        __syncthreads();

        if (t < 128) {
            const int rt = t >> 2, ct = t & 3;
            const int rb = rt << 2;
            const int physc = ((ct ^ ((rt ^ (rt >> 3)) & 3)) << 2);
            float* sp0 = sS + rb * 16 + physc;
            ulonglong2 s0 = *(const ulonglong2*)(sp0);
            ulonglong2 s1 = *(const ulonglong2*)(sp0 + 16);
            ulonglong2 s2v = *(const ulonglong2*)(sp0 + 32);
            ulonglong2 s3 = *(const ulonglong2*)(sp0 + 48);
            const float* kp = B + OFF_K + rb;
            const float* up2 = bu + (ct << 2);
            #pragma unroll 8
            for (int j = 0; j < 32; j++) {
                float4 k4 = *(const float4*)kp;
                ulonglong2 u2 = *(const ulonglong2*)up2;
                fm2(s0.x,  pk1(k4.x), u2.x); fm2(s0.y,  pk1(k4.x), u2.y);
                fm2(s1.x,  pk1(k4.y), u2.x); fm2(s1.y,  pk1(k4.y), u2.y);
                fm2(s2v.x, pk1(k4.z), u2.x); fm2(s2v.y, pk1(k4.z), u2.y);
                fm2(s3.x,  pk1(k4.w), u2.x); fm2(s3.y,  pk1(k4.w), u2.y);
                kp += 128; up2 += 16;
            }
            *(ulonglong2*)(sp0)      = s0;
            *(ulonglong2*)(sp0 + 16) = s1;
            *(ulonglong2*)(sp0 + 32) = s2v;
            *(ulonglong2*)(sp0 + 48) = s3;
        } else {
            const int ii2 = (t - 128) >> 2, cq = t & 3;
            const int asw = ii2 & 7;
            ulonglong2 acc = *(const ulonglong2*)(po + ii2 * 16 + (cq << 2));
            const float* atr = B + OFF_AT + ii2 * 32;
            const float* Up = bu + (cq << 2);
            #pragma unroll
            for (int j4 = 0; j4 < 8; j4++) {
                float4 a4 = *(const float4*)(atr + ((j4 ^ asw) << 2));
                const float* u0p = Up + (j4 << 6);
                ulonglong2 U0 = *(const ulonglong2*)(u0p);
                ulonglong2 U1 = *(const ulonglong2*)(u0p + 16);
                ulonglong2 U2 = *(const ulonglong2*)(u0p + 32);
                ulonglong2 U3 = *(const ulonglong2*)(u0p + 48);
                fm2(acc.x, pk1(a4.x), U0.x); fm2(acc.y, pk1(a4.x), U0.y);
                fm2(acc.x, pk1(a4.y), U1.x); fm2(acc.y, pk1(a4.y), U1.y);
                fm2(acc.x, pk1(a4.z), U2.x); fm2(acc.y, pk1(a4.z), U2.y);
                fm2(acc.x, pk1(a4.w), U3.x); fm2(acc.y, pk1(a4.w), U3.y);
            }
            float2 f0 = upk(acc.x), f1 = upk(acc.y);
            size_t off = ((size_t)bh * LL + (size_t)ch * CC + ii2) * 128 + c0 + (cq << 2);
            *(float4*)(out + off) = make_float4(f0.x, f0.y, f1.x, f1.y);
        }
    }

    if (Sout != nullptr) {
        __syncthreads();
        size_t sb = (size_t)bh * 128 * 128;
        for (int idx = t; idx < 2048; idx += 256) {
            int r = idx >> 4, c = idx & 15;
            int phys = ((((c >> 2) ^ ((r >> 2) & 3) ^ ((r >> 5) & 3)) & 3) << 2) + (c & 3);
            Sout[sb + (size_t)r * 128 + c0 + c] = sS[r * 16 + phys];
        }
    }
}

// =====================================================================
#define P1_SMEM ((3 * CC * SDK + CC * (CC + 1) + 3 * CC) * (int)sizeof(float))
#define P2_SMEM ((4 + 2048 + 512 + 2 * BUF_F) * (int)sizeof(float))

extern "C" void kernel_launch(void* const* d_in, const int* in_sizes, int n_in,
                              void* d_out, int out_size)
{
    const float* q    = (const float*)d_in[0];
    const float* k    = (const float*)d_in[1];
    const float* v    = (const float*)d_in[2];
    const float* beta = (const float*)d_in[3];
    float* out = (float*)d_out;
    float* Sout = ((size_t)out_size >= OUT_ELEMS + S_ELEMS) ? (out + OUT_ELEMS) : nullptr;

    cudaFuncSetAttribute(phase1_kernel, cudaFuncAttributeMaxDynamicSharedMemorySize, P1_SMEM);
    cudaFuncSetAttribute(phase2_kernel, cudaFuncAttributeMaxDynamicSharedMemorySize, P2_SMEM);

    phase1_kernel<<<dim3(NCH, BHT), 256, P1_SMEM>>>(q, k, v, beta);
    phase2_kernel<<<dim3(8, BHT), 256, P2_SMEM>>>(out, Sout);
}